// round 1
// baseline (speedup 1.0000x reference)
#include <cuda_runtime.h>
#include <cstdint>
#include <cstddef>

// Problem constants
#define PB   4
#define PLQ  1024
#define PLK  2048
#define PE   512
#define PHID 512
#define PH   8
#define PHD  64

// ---------------------------------------------------------------------------
// Scratch (no runtime allocation allowed -> __device__ globals)
// ---------------------------------------------------------------------------
__device__ float g_S [(size_t)PB * PH * PLQ * PLK];  // 64M floats: scores (cross), reused for self
__device__ float g_QM[PB * PLQ * PE];                // masked queries
__device__ float g_Qp[PB * PLQ * PE];                // Q proj (cross or self)
__device__ float g_Kp[PB * PLK * PE];                // K proj
__device__ float g_Vp[PB * PLK * PE];                // V proj
__device__ float g_Op[PB * PLQ * PE];                // attention output (head-concat)
__device__ float g_Pp[PB * PLQ * PE];                // out-projection result
__device__ float g_X1[PB * PLQ * PE];                // after cross block LN
__device__ float g_Fb[PB * PLQ * PHID];              // FFN
__device__ float g_X2[PB * PLQ * PHID];              // after FFN LN (self-attn input)

// ---------------------------------------------------------------------------
// Generic tiled SGEMM: C = alpha * A @ op(B) + bias
//   B_TRANS=1: B is [N,K] row-major (C[m,n] = sum_k A[m,k]*B[n,k])  -- "x @ W^T"
//   B_TRANS=0: B is [K,N] row-major (C[m,n] = sum_k A[m,k]*B[k,n])
// Batched over blockIdx.z with (b,h) split strides: off = (z/Hdiv)*s_b + (z%Hdiv)*s_h
// Requires M%128==0, N%64==0, K%16==0, all pointers/ld 16B-friendly.
// ---------------------------------------------------------------------------
template<int B_TRANS>
__global__ __launch_bounds__(256)
void sgemm_kernel(const float* __restrict__ A, int lda, long sAb, long sAh,
                  const float* __restrict__ Bm, int ldb, long sBb, long sBh,
                  float* __restrict__ C, int ldc, long sCb, long sCh,
                  const float* __restrict__ bias,
                  int M, int N, int K, float alpha, int Hdiv)
{
    const int z  = blockIdx.z;
    const int zb = z / Hdiv, zh = z % Hdiv;
    A  += (size_t)zb * sAb + (size_t)zh * sAh;
    Bm += (size_t)zb * sBb + (size_t)zh * sBh;
    C  += (size_t)zb * sCb + (size_t)zh * sCh;

    constexpr int BM = 128, BN = 64, BK = 16;
    __shared__ float As[BK][BM];
    __shared__ float Bs[BK][BN];

    const int m0  = blockIdx.y * BM;
    const int n0  = blockIdx.x * BN;
    const int tx  = threadIdx.x;
    const int tm0 = (tx >> 4) * 8;   // 16 groups of 8 rows
    const int tn0 = (tx & 15) * 4;   // 16 groups of 4 cols

    float acc[8][4];
    #pragma unroll
    for (int i = 0; i < 8; i++)
        #pragma unroll
        for (int j = 0; j < 4; j++) acc[i][j] = 0.f;

    for (int k0 = 0; k0 < K; k0 += BK) {
        // Load A tile (128x16), transposed into As[k][m]. 512 float4 / 256 thr.
        #pragma unroll
        for (int l = 0; l < 2; l++) {
            int fid = tx + l * 256;
            int row = fid >> 2;
            int kc  = (fid & 3) * 4;
            float4 v = *reinterpret_cast<const float4*>(A + (size_t)(m0 + row) * lda + k0 + kc);
            As[kc + 0][row] = v.x; As[kc + 1][row] = v.y;
            As[kc + 2][row] = v.z; As[kc + 3][row] = v.w;
        }
        // Load B tile
        if (B_TRANS) {
            int row = tx >> 2;            // n within tile, 0..63
            int kc  = (tx & 3) * 4;
            float4 v = *reinterpret_cast<const float4*>(Bm + (size_t)(n0 + row) * ldb + k0 + kc);
            Bs[kc + 0][row] = v.x; Bs[kc + 1][row] = v.y;
            Bs[kc + 2][row] = v.z; Bs[kc + 3][row] = v.w;
        } else {
            int kr = tx >> 4;             // 0..15
            int nc = (tx & 15) * 4;
            float4 v = *reinterpret_cast<const float4*>(Bm + (size_t)(k0 + kr) * ldb + n0 + nc);
            *reinterpret_cast<float4*>(&Bs[kr][nc]) = v;
        }
        __syncthreads();

        #pragma unroll
        for (int kk = 0; kk < BK; kk++) {
            float a[8], bb[4];
            #pragma unroll
            for (int i = 0; i < 8; i++) a[i] = As[kk][tm0 + i];
            #pragma unroll
            for (int j = 0; j < 4; j++) bb[j] = Bs[kk][tn0 + j];
            #pragma unroll
            for (int i = 0; i < 8; i++)
                #pragma unroll
                for (int j = 0; j < 4; j++) acc[i][j] += a[i] * bb[j];
        }
        __syncthreads();
    }

    float bv[4] = {0.f, 0.f, 0.f, 0.f};
    if (bias) {
        #pragma unroll
        for (int j = 0; j < 4; j++) bv[j] = bias[n0 + tn0 + j];
    }
    #pragma unroll
    for (int i = 0; i < 8; i++) {
        float4 o;
        o.x = acc[i][0] * alpha + bv[0];
        o.y = acc[i][1] * alpha + bv[1];
        o.z = acc[i][2] * alpha + bv[2];
        o.w = acc[i][3] * alpha + bv[3];
        *reinterpret_cast<float4*>(C + (size_t)(m0 + tm0 + i) * ldc + n0 + tn0) = o;
    }
}

// ---------------------------------------------------------------------------
// Mask invalid query rows to zero: out[r,:] = (r%LQ < q_len[r/LQ]) ? in : 0
// grid = B*LQ rows, 128 threads, float4
// ---------------------------------------------------------------------------
__global__ void mask_rows_kernel(const float* __restrict__ in, float* __restrict__ out,
                                 const int* __restrict__ q_len)
{
    int r = blockIdx.x;
    bool valid = (r % PLQ) < q_len[r / PLQ];
    const float4* src = reinterpret_cast<const float4*>(in + (size_t)r * PE);
    float4* dst = reinterpret_cast<float4*>(out + (size_t)r * PE);
    float4 z4 = make_float4(0.f, 0.f, 0.f, 0.f);
    for (int c = threadIdx.x; c < PE / 4; c += blockDim.x)
        dst[c] = valid ? src[c] : z4;
}

// ---------------------------------------------------------------------------
// Row softmax (in place). Rows of length rowlen. Optional key mask: only
// k < q_len[b] participate (b = row / rows_per_b); masked tail written as 0.
// grid = nrows, 256 threads.
// ---------------------------------------------------------------------------
__global__ __launch_bounds__(256)
void softmax_kernel(float* __restrict__ S, int rowlen, int masked,
                    const int* __restrict__ q_len, int rows_per_b)
{
    int r = blockIdx.x;
    float* row = S + (size_t)r * rowlen;
    int limit = rowlen;
    if (masked) limit = q_len[r / rows_per_b];

    int tid = threadIdx.x;
    __shared__ float sred[256];

    float mx = -3.4e38f;
    for (int k = tid; k < limit; k += 256) mx = fmaxf(mx, row[k]);
    sred[tid] = mx; __syncthreads();
    for (int s = 128; s > 0; s >>= 1) {
        if (tid < s) sred[tid] = fmaxf(sred[tid], sred[tid + s]);
        __syncthreads();
    }
    mx = sred[0]; __syncthreads();

    float sum = 0.f;
    for (int k = tid; k < limit; k += 256) {
        float e = __expf(row[k] - mx);
        row[k] = e;
        sum += e;
    }
    sred[tid] = sum; __syncthreads();
    for (int s = 128; s > 0; s >>= 1) {
        if (tid < s) sred[tid] += sred[tid + s];
        __syncthreads();
    }
    float inv = 1.0f / sred[0];

    for (int k = tid; k < limit; k += 256) row[k] *= inv;
    for (int k = limit + tid; k < rowlen; k += 256) row[k] = 0.f;
}

// ---------------------------------------------------------------------------
// weights output: wout[b,q,k] = valid(q) ? mean_h S[(b*H+h),q,k] : 0
// grid = B*LQ, 256 threads
// ---------------------------------------------------------------------------
__global__ __launch_bounds__(256)
void weights_kernel(const float* __restrict__ S, const int* __restrict__ q_len,
                    float* __restrict__ wout)
{
    int r = blockIdx.x;
    int b = r / PLQ, q = r % PLQ;
    float* out = wout + (size_t)r * PLK;
    if (q >= q_len[b]) {
        for (int k = threadIdx.x; k < PLK; k += 256) out[k] = 0.f;
        return;
    }
    const float* base = S + ((size_t)b * PH) * PLQ * PLK + (size_t)q * PLK;
    for (int k = threadIdx.x; k < PLK; k += 256) {
        float s = 0.f;
        #pragma unroll
        for (int h = 0; h < PH; h++) s += base[(size_t)h * PLQ * PLK + k];
        out[k] = s * (1.0f / PH);
    }
}

// ---------------------------------------------------------------------------
// out[r,:] = LN( silu(X[r,:] + Y[r,:]) ) * g + b   ; optional zero invalid rows
// D = 512. grid = B*LQ rows, 128 threads, 4 elems (float4) per thread.
// ---------------------------------------------------------------------------
__global__ __launch_bounds__(128)
void add_silu_ln_kernel(const float* __restrict__ X, const float* __restrict__ Y,
                        const float* __restrict__ g, const float* __restrict__ bln,
                        float* __restrict__ out, const int* __restrict__ q_len,
                        int zero_invalid)
{
    constexpr int D = 512;
    int r = blockIdx.x;
    int tid = threadIdx.x;
    int c = tid * 4;

    float4 x = *reinterpret_cast<const float4*>(X + (size_t)r * D + c);
    float4 y = *reinterpret_cast<const float4*>(Y + (size_t)r * D + c);
    float v[4] = {x.x + y.x, x.y + y.y, x.z + y.z, x.w + y.w};

    float s[4], sum = 0.f, sumsq = 0.f;
    #pragma unroll
    for (int i = 0; i < 4; i++) {
        s[i] = v[i] / (1.0f + __expf(-v[i]));   // silu
        sum += s[i];
        sumsq += s[i] * s[i];
    }

    __shared__ float r1[128], r2[128];
    r1[tid] = sum; r2[tid] = sumsq; __syncthreads();
    for (int st = 64; st > 0; st >>= 1) {
        if (tid < st) { r1[tid] += r1[tid + st]; r2[tid] += r2[tid + st]; }
        __syncthreads();
    }
    float mu  = r1[0] * (1.0f / D);
    float var = r2[0] * (1.0f / D) - mu * mu;
    float rs  = rsqrtf(var + 1e-5f);

    bool zero = zero_invalid && ((r % PLQ) >= q_len[r / PLQ]);

    float4 gg = *reinterpret_cast<const float4*>(g + c);
    float4 bb = *reinterpret_cast<const float4*>(bln + c);
    float4 o;
    o.x = zero ? 0.f : (s[0] - mu) * rs * gg.x + bb.x;
    o.y = zero ? 0.f : (s[1] - mu) * rs * gg.y + bb.y;
    o.z = zero ? 0.f : (s[2] - mu) * rs * gg.z + bb.z;
    o.w = zero ? 0.f : (s[3] - mu) * rs * gg.w + bb.w;
    *reinterpret_cast<float4*>(out + (size_t)r * D + c) = o;
}

// ---------------------------------------------------------------------------
// Host launcher
// ---------------------------------------------------------------------------
static void launch_gemm(bool btrans,
                        const float* A, int lda, long sAb, long sAh,
                        const float* Bm, int ldb, long sBb, long sBh,
                        float* C, int ldc, long sCb, long sCh,
                        const float* bias, int M, int N, int K,
                        float alpha, int Z, int Hdiv)
{
    dim3 grid(N / 64, M / 128, Z);
    if (btrans)
        sgemm_kernel<1><<<grid, 256>>>(A, lda, sAb, sAh, Bm, ldb, sBb, sBh,
                                       C, ldc, sCb, sCh, bias, M, N, K, alpha, Hdiv);
    else
        sgemm_kernel<0><<<grid, 256>>>(A, lda, sAb, sAh, Bm, ldb, sBb, sBh,
                                       C, ldc, sCb, sCh, bias, M, N, K, alpha, Hdiv);
}

extern "C" void kernel_launch(void* const* d_in, const int* in_sizes, int n_in,
                              void* d_out, int out_size)
{
    const float* queries = (const float*)d_in[0];
    const float* keys    = (const float*)d_in[1];
    const int*   q_len   = (const int*)  d_in[2];
    const float* cWq = (const float*)d_in[3];  const float* cbq = (const float*)d_in[4];
    const float* cWk = (const float*)d_in[5];  const float* cbk = (const float*)d_in[6];
    const float* cWv = (const float*)d_in[7];  const float* cbv = (const float*)d_in[8];
    const float* cWo = (const float*)d_in[9];  const float* cbo = (const float*)d_in[10];
    const float* sWq = (const float*)d_in[11]; const float* sbq = (const float*)d_in[12];
    const float* sWk = (const float*)d_in[13]; const float* sbk = (const float*)d_in[14];
    const float* sWv = (const float*)d_in[15]; const float* sbv = (const float*)d_in[16];
    const float* sWo = (const float*)d_in[17]; const float* sbo = (const float*)d_in[18];
    const float* Wf  = (const float*)d_in[19]; const float* bf  = (const float*)d_in[20];
    const float* g_cross = (const float*)d_in[21]; const float* b_cross = (const float*)d_in[22];
    const float* g_ffn   = (const float*)d_in[23]; const float* b_ffn   = (const float*)d_in[24];
    const float* g_self  = (const float*)d_in[25]; const float* b_self  = (const float*)d_in[26];

    float* out_q = (float*)d_out;
    float* out_w = out_q + (size_t)PB * PLQ * PHID;

    float *S, *QM, *Qp, *Kp, *Vp, *Op, *Pp, *X1, *Fb, *X2;
    cudaGetSymbolAddress((void**)&S,  g_S);
    cudaGetSymbolAddress((void**)&QM, g_QM);
    cudaGetSymbolAddress((void**)&Qp, g_Qp);
    cudaGetSymbolAddress((void**)&Kp, g_Kp);
    cudaGetSymbolAddress((void**)&Vp, g_Vp);
    cudaGetSymbolAddress((void**)&Op, g_Op);
    cudaGetSymbolAddress((void**)&Pp, g_Pp);
    cudaGetSymbolAddress((void**)&X1, g_X1);
    cudaGetSymbolAddress((void**)&Fb, g_Fb);
    cudaGetSymbolAddress((void**)&X2, g_X2);

    const int MQ = PB * PLQ;   // 4096
    const int MK = PB * PLK;   // 8192
    const long sQb = (long)PLQ * PE, sKb = (long)PLK * PE;
    const long sScrC = (long)PH * PLQ * PLK, sScrH = (long)PLQ * PLK;   // cross scores
    const long sSsC  = (long)PH * PLQ * PLQ, sSsH  = (long)PLQ * PLQ;   // self scores
    const float scale = 0.125f;  // 1/sqrt(64)

    // 1) masked queries
    mask_rows_kernel<<<MQ, 128>>>(queries, QM, q_len);

    // 2) cross projections
    launch_gemm(true, QM,   PE, 0,0, cWq, PE, 0,0, Qp, PE, 0,0, cbq, MQ, PE, PE, 1.f, 1, 1);
    launch_gemm(true, keys, PE, 0,0, cWk, PE, 0,0, Kp, PE, 0,0, cbk, MK, PE, PE, 1.f, 1, 1);
    launch_gemm(true, keys, PE, 0,0, cWv, PE, 0,0, Vp, PE, 0,0, cbv, MK, PE, PE, 1.f, 1, 1);

    // 3) cross scores S[b,h,q,k] = scale * Q·K   (Z = B*H)
    launch_gemm(true, Qp, PE, sQb, PHD, Kp, PE, sKb, PHD,
                S, PLK, sScrC, sScrH, nullptr, PLQ, PLK, PHD, scale, PB * PH, PH);

    // 4) softmax over LK (no key mask in cross)
    softmax_kernel<<<PB * PH * PLQ, 256>>>(S, PLK, 0, q_len, PH * PLQ);

    // 5) weights output (mean over heads, invalid q rows -> 0)
    weights_kernel<<<MQ, 256>>>(S, q_len, out_w);

    // 6) O = W @ V  (B as [K,N]: V rows are keys)
    launch_gemm(false, S, PLK, sScrC, sScrH, Vp, PE, sKb, PHD,
                Op, PE, sQb, PHD, nullptr, PLQ, PHD, PLK, 1.f, PB * PH, PH);

    // 7) cross out-projection
    launch_gemm(true, Op, PE, 0,0, cWo, PE, 0,0, Pp, PE, 0,0, cbo, MQ, PE, PE, 1.f, 1, 1);

    // 8) x1 = LN(silu(cross + qm))
    add_silu_ln_kernel<<<MQ, 128>>>(Pp, QM, g_cross, b_cross, X1, q_len, 0);

    // 9) FFN + LN
    launch_gemm(true, X1, PE, 0,0, Wf, PE, 0,0, Fb, PHID, 0,0, bf, MQ, PHID, PE, 1.f, 1, 1);
    add_silu_ln_kernel<<<MQ, 128>>>(X1, Fb, g_ffn, b_ffn, X2, q_len, 0);

    // 10) self projections (reuse Q/K/V buffers; only first 4096 rows used)
    launch_gemm(true, X2, PHID, 0,0, sWq, PHID, 0,0, Qp, PHID, 0,0, sbq, MQ, PHID, PHID, 1.f, 1, 1);
    launch_gemm(true, X2, PHID, 0,0, sWk, PHID, 0,0, Kp, PHID, 0,0, sbk, MQ, PHID, PHID, 1.f, 1, 1);
    launch_gemm(true, X2, PHID, 0,0, sWv, PHID, 0,0, Vp, PHID, 0,0, sbv, MQ, PHID, PHID, 1.f, 1, 1);

    // 11) self scores (Z = B*H), keys stride = LQ rows now
    launch_gemm(true, Qp, PHID, sQb, PHD, Kp, PHID, sQb, PHD,
                S, PLQ, sSsC, sSsH, nullptr, PLQ, PLQ, PHD, scale, PB * PH, PH);

    // 12) masked softmax over LQ: only k < q_len[b] participate
    softmax_kernel<<<PB * PH * PLQ, 256>>>(S, PLQ, 1, q_len, PH * PLQ);

    // 13) O2 = W2 @ V
    launch_gemm(false, S, PLQ, sSsC, sSsH, Vp, PHID, sQb, PHD,
                Op, PHID, sQb, PHD, nullptr, PLQ, PHD, PLQ, 1.f, PB * PH, PH);

    // 14) self out-projection
    launch_gemm(true, Op, PHID, 0,0, sWo, PHID, 0,0, Pp, PHID, 0,0, sbo, MQ, PHID, PHID, 1.f, 1, 1);

    // 15) final: out = LN(silu(x2 + so)), invalid rows zeroed
    add_silu_ln_kernel<<<MQ, 128>>>(X2, Pp, g_self, b_self, out_q, q_len, 1);
}

// round 2
// speedup vs baseline: 2.3719x; 2.3719x over previous
#include <cuda_runtime.h>
#include <cuda_fp16.h>
#include <cstdint>
#include <cstddef>

// Problem constants
#define PB   4
#define PLQ  1024
#define PLK  2048
#define PE   512
#define PHID 512
#define PH   8
#define PHD  64

// ---------------------------------------------------------------------------
// Scratch (no runtime allocation allowed -> __device__ globals)
// ---------------------------------------------------------------------------
__device__ float g_S [(size_t)PB * PH * PLQ * PLK];  // 64M floats: scores (cross), reused for self
__device__ float g_QM[PB * PLQ * PE];                // masked queries
__device__ float g_Qp[PB * PLQ * PE];                // Q proj (cross or self)
__device__ float g_Kp[PB * PLK * PE];                // K proj
__device__ float g_Vp[PB * PLK * PE];                // V proj
__device__ float g_Op[PB * PLQ * PE];                // attention output (head-concat)
__device__ float g_Pp[PB * PLQ * PE];                // out-projection result
__device__ float g_X1[PB * PLQ * PE];                // after cross block LN
__device__ float g_Fb[PB * PLQ * PHID];              // FFN
__device__ float g_X2[PB * PLQ * PHID];              // after FFN LN (self-attn input)

// ---------------------------------------------------------------------------
// Tensor-core HGEMM: C = alpha * A @ op(B) + bias   (fp32 in/out, fp16 MMA, fp32 accum)
//   B_TRANS=1: B is [N,K] row-major (C[m,n] = sum_k A[m,k]*B[n,k])  -- "x @ W^T"
//   B_TRANS=0: B is [K,N] row-major (C[m,n] = sum_k A[m,k]*B[k,n])
// Batched over blockIdx.z: off = (z/Hdiv)*s_b + (z%Hdiv)*s_h
// Requires M%128==0, N%64==0, K%64==0, rows 16B-aligned.
//
// CTA tile 128x64x64, 8 warps in 4(M)x2(N), warp tile 32x32,
// mma.sync.m16n8k16 (2x4 mma tiles per warp). Smem XOR-swizzled for
// conflict-free ldmatrix.
// ---------------------------------------------------------------------------
template<int B_TRANS>
__global__ __launch_bounds__(256)
void hgemm_kernel(const float* __restrict__ A, int lda, long sAb, long sAh,
                  const float* __restrict__ Bm, int ldb, long sBb, long sBh,
                  float* __restrict__ C, int ldc, long sCb, long sCh,
                  const float* __restrict__ bias,
                  int M, int N, int K, float alpha, int Hdiv)
{
    const int z  = blockIdx.z;
    const int zb = z / Hdiv, zh = z % Hdiv;
    A  += (size_t)zb * sAb + (size_t)zh * sAh;
    Bm += (size_t)zb * sBb + (size_t)zh * sBh;
    C  += (size_t)zb * sCb + (size_t)zh * sCh;

    constexpr int BM = 128, BN = 64, BK = 64;
    // swizzled layout: row of 64 halves = 128 bytes; 16B chunk index XOR (row&7)
    __shared__ alignas(16) __half sA[BM * BK];
    __shared__ alignas(16) __half sB[BN * BK];
    char* sAb_ = reinterpret_cast<char*>(sA);
    char* sBb_ = reinterpret_cast<char*>(sB);
    const uint32_t baseA = (uint32_t)__cvta_generic_to_shared(sA);
    const uint32_t baseB = (uint32_t)__cvta_generic_to_shared(sB);

    const int tid  = threadIdx.x;
    const int lane = tid & 31;
    const int warp = tid >> 5;
    const int wm   = warp & 3;   // 0..3 -> M offset wm*32
    const int wn   = warp >> 2;  // 0..1 -> N offset wn*32
    const int m0   = blockIdx.y * BM;
    const int n0   = blockIdx.x * BN;

    float d[2][4][4];
    #pragma unroll
    for (int mi = 0; mi < 2; mi++)
        #pragma unroll
        for (int ni = 0; ni < 4; ni++)
            #pragma unroll
            for (int j = 0; j < 4; j++) d[mi][ni][j] = 0.f;

    for (int k0 = 0; k0 < K; k0 += BK) {
        // ---- load A tile (128x64 floats -> fp16, swizzled) : 2048 float4 ----
        #pragma unroll
        for (int i = 0; i < 8; i++) {
            int f = tid + i * 256;
            int r = f >> 4;              // 0..127
            int c = (f & 15) * 4;        // 0..60
            float4 v = *reinterpret_cast<const float4*>(A + (size_t)(m0 + r) * lda + k0 + c);
            uint32_t off = (uint32_t)r * 128u + (uint32_t)(((c >> 3) ^ (r & 7)) << 4) + (uint32_t)((c & 7) << 1);
            __half2* p = reinterpret_cast<__half2*>(sAb_ + off);
            p[0] = __floats2half2_rn(v.x, v.y);
            p[1] = __floats2half2_rn(v.z, v.w);
        }
        // ---- load B tile as BT[n][k] (64x64) ----
        if (B_TRANS) {
            #pragma unroll
            for (int i = 0; i < 4; i++) {
                int f = tid + i * 256;
                int r = f >> 4;          // n: 0..63
                int c = (f & 15) * 4;    // k
                float4 v = *reinterpret_cast<const float4*>(Bm + (size_t)(n0 + r) * ldb + k0 + c);
                uint32_t off = (uint32_t)r * 128u + (uint32_t)(((c >> 3) ^ (r & 7)) << 4) + (uint32_t)((c & 7) << 1);
                __half2* p = reinterpret_cast<__half2*>(sBb_ + off);
                p[0] = __floats2half2_rn(v.x, v.y);
                p[1] = __floats2half2_rn(v.z, v.w);
            }
        } else {
            #pragma unroll
            for (int i = 0; i < 4; i++) {
                int f = tid + i * 256;
                int kk = f >> 4;         // k: 0..63
                int c  = (f & 15) * 4;   // n
                float4 v = *reinterpret_cast<const float4*>(Bm + (size_t)(k0 + kk) * ldb + n0 + c);
                float vv[4] = {v.x, v.y, v.z, v.w};
                #pragma unroll
                for (int j = 0; j < 4; j++) {
                    int r = c + j;       // n row in BT
                    uint32_t off = (uint32_t)r * 128u + (uint32_t)(((kk >> 3) ^ (r & 7)) << 4) + (uint32_t)((kk & 7) << 1);
                    *reinterpret_cast<__half*>(sBb_ + off) = __float2half_rn(vv[j]);
                }
            }
        }
        __syncthreads();

        // ---- compute: 4 k-steps of 16 ----
        #pragma unroll
        for (int ks = 0; ks < 4; ks++) {
            const int kb = ks * 16;
            uint32_t a[2][4], b[4][2];
            #pragma unroll
            for (int mi = 0; mi < 2; mi++) {
                int r  = wm * 32 + mi * 16 + (lane & 15);
                int ck = kb + ((lane >> 4) << 3);
                uint32_t addr = baseA + (uint32_t)r * 128u + (uint32_t)((((ck >> 3) ^ (r & 7))) << 4);
                asm volatile("ldmatrix.sync.aligned.m8n8.x4.shared.b16 {%0,%1,%2,%3}, [%4];"
                             : "=r"(a[mi][0]), "=r"(a[mi][1]), "=r"(a[mi][2]), "=r"(a[mi][3])
                             : "r"(addr));
            }
            #pragma unroll
            for (int ni = 0; ni < 4; ni++) {
                int r  = wn * 32 + ni * 8 + (lane & 7);
                int ck = kb + (((lane >> 3) & 1) << 3);
                uint32_t addr = baseB + (uint32_t)r * 128u + (uint32_t)((((ck >> 3) ^ (r & 7))) << 4);
                asm volatile("ldmatrix.sync.aligned.m8n8.x2.shared.b16 {%0,%1}, [%2];"
                             : "=r"(b[ni][0]), "=r"(b[ni][1])
                             : "r"(addr));
            }
            #pragma unroll
            for (int mi = 0; mi < 2; mi++)
                #pragma unroll
                for (int ni = 0; ni < 4; ni++) {
                    asm volatile(
                        "mma.sync.aligned.m16n8k16.row.col.f32.f16.f16.f32 "
                        "{%0,%1,%2,%3}, {%4,%5,%6,%7}, {%8,%9}, {%0,%1,%2,%3};"
                        : "+f"(d[mi][ni][0]), "+f"(d[mi][ni][1]),
                          "+f"(d[mi][ni][2]), "+f"(d[mi][ni][3])
                        : "r"(a[mi][0]), "r"(a[mi][1]), "r"(a[mi][2]), "r"(a[mi][3]),
                          "r"(b[ni][0]), "r"(b[ni][1]));
                }
        }
        __syncthreads();
    }

    // ---- epilogue ----
    const int g = lane >> 2, t = lane & 3;
    #pragma unroll
    for (int mi = 0; mi < 2; mi++) {
        #pragma unroll
        for (int ni = 0; ni < 4; ni++) {
            int rr = m0 + wm * 32 + mi * 16 + g;
            int cc = n0 + wn * 32 + ni * 8 + t * 2;
            float b0 = 0.f, b1 = 0.f;
            if (bias) { b0 = bias[cc]; b1 = bias[cc + 1]; }
            float2 o0 = make_float2(d[mi][ni][0] * alpha + b0, d[mi][ni][1] * alpha + b1);
            float2 o1 = make_float2(d[mi][ni][2] * alpha + b0, d[mi][ni][3] * alpha + b1);
            *reinterpret_cast<float2*>(C + (size_t)rr * ldc + cc)       = o0;
            *reinterpret_cast<float2*>(C + (size_t)(rr + 8) * ldc + cc) = o1;
        }
    }
}

// ---------------------------------------------------------------------------
// Mask invalid query rows to zero: out[r,:] = (r%LQ < q_len[r/LQ]) ? in : 0
// ---------------------------------------------------------------------------
__global__ void mask_rows_kernel(const float* __restrict__ in, float* __restrict__ out,
                                 const int* __restrict__ q_len)
{
    int r = blockIdx.x;
    bool valid = (r % PLQ) < q_len[r / PLQ];
    const float4* src = reinterpret_cast<const float4*>(in + (size_t)r * PE);
    float4* dst = reinterpret_cast<float4*>(out + (size_t)r * PE);
    float4 z4 = make_float4(0.f, 0.f, 0.f, 0.f);
    for (int c = threadIdx.x; c < PE / 4; c += blockDim.x)
        dst[c] = valid ? src[c] : z4;
}

// ---------------------------------------------------------------------------
// Row softmax (in place), optional key-length mask; masked tail written as 0.
// ---------------------------------------------------------------------------
__global__ __launch_bounds__(256)
void softmax_kernel(float* __restrict__ S, int rowlen, int masked,
                    const int* __restrict__ q_len, int rows_per_b)
{
    int r = blockIdx.x;
    float* row = S + (size_t)r * rowlen;
    int limit = rowlen;
    if (masked) limit = q_len[r / rows_per_b];

    int tid = threadIdx.x;
    __shared__ float sred[256];

    float mx = -3.4e38f;
    for (int k = tid; k < limit; k += 256) mx = fmaxf(mx, row[k]);
    sred[tid] = mx; __syncthreads();
    for (int s = 128; s > 0; s >>= 1) {
        if (tid < s) sred[tid] = fmaxf(sred[tid], sred[tid + s]);
        __syncthreads();
    }
    mx = sred[0]; __syncthreads();

    float sum = 0.f;
    for (int k = tid; k < limit; k += 256) {
        float e = __expf(row[k] - mx);
        row[k] = e;
        sum += e;
    }
    sred[tid] = sum; __syncthreads();
    for (int s = 128; s > 0; s >>= 1) {
        if (tid < s) sred[tid] += sred[tid + s];
        __syncthreads();
    }
    float inv = 1.0f / sred[0];

    for (int k = tid; k < limit; k += 256) row[k] *= inv;
    for (int k = limit + tid; k < rowlen; k += 256) row[k] = 0.f;
}

// ---------------------------------------------------------------------------
// weights output: wout[b,q,k] = valid(q) ? mean_h S[(b*H+h),q,k] : 0
// ---------------------------------------------------------------------------
__global__ __launch_bounds__(256)
void weights_kernel(const float* __restrict__ S, const int* __restrict__ q_len,
                    float* __restrict__ wout)
{
    int r = blockIdx.x;
    int b = r / PLQ, q = r % PLQ;
    float* out = wout + (size_t)r * PLK;
    if (q >= q_len[b]) {
        for (int k = threadIdx.x; k < PLK; k += 256) out[k] = 0.f;
        return;
    }
    const float* base = S + ((size_t)b * PH) * PLQ * PLK + (size_t)q * PLK;
    for (int k = threadIdx.x; k < PLK; k += 256) {
        float s = 0.f;
        #pragma unroll
        for (int h = 0; h < PH; h++) s += base[(size_t)h * PLQ * PLK + k];
        out[k] = s * (1.0f / PH);
    }
}

// ---------------------------------------------------------------------------
// out[r,:] = LN( silu(X[r,:] + Y[r,:]) ) * g + b ; optional zero invalid rows
// ---------------------------------------------------------------------------
__global__ __launch_bounds__(128)
void add_silu_ln_kernel(const float* __restrict__ X, const float* __restrict__ Y,
                        const float* __restrict__ g, const float* __restrict__ bln,
                        float* __restrict__ out, const int* __restrict__ q_len,
                        int zero_invalid)
{
    constexpr int D = 512;
    int r = blockIdx.x;
    int tid = threadIdx.x;
    int c = tid * 4;

    float4 x = *reinterpret_cast<const float4*>(X + (size_t)r * D + c);
    float4 y = *reinterpret_cast<const float4*>(Y + (size_t)r * D + c);
    float v[4] = {x.x + y.x, x.y + y.y, x.z + y.z, x.w + y.w};

    float s[4], sum = 0.f, sumsq = 0.f;
    #pragma unroll
    for (int i = 0; i < 4; i++) {
        s[i] = v[i] / (1.0f + __expf(-v[i]));
        sum += s[i];
        sumsq += s[i] * s[i];
    }

    __shared__ float r1[128], r2[128];
    r1[tid] = sum; r2[tid] = sumsq; __syncthreads();
    for (int st = 64; st > 0; st >>= 1) {
        if (tid < st) { r1[tid] += r1[tid + st]; r2[tid] += r2[tid + st]; }
        __syncthreads();
    }
    float mu  = r1[0] * (1.0f / D);
    float var = r2[0] * (1.0f / D) - mu * mu;
    float rs  = rsqrtf(var + 1e-5f);

    bool zero = zero_invalid && ((r % PLQ) >= q_len[r / PLQ]);

    float4 gg = *reinterpret_cast<const float4*>(g + c);
    float4 bb = *reinterpret_cast<const float4*>(bln + c);
    float4 o;
    o.x = zero ? 0.f : (s[0] - mu) * rs * gg.x + bb.x;
    o.y = zero ? 0.f : (s[1] - mu) * rs * gg.y + bb.y;
    o.z = zero ? 0.f : (s[2] - mu) * rs * gg.z + bb.z;
    o.w = zero ? 0.f : (s[3] - mu) * rs * gg.w + bb.w;
    *reinterpret_cast<float4*>(out + (size_t)r * D + c) = o;
}

// ---------------------------------------------------------------------------
// Host launcher
// ---------------------------------------------------------------------------
static void launch_gemm(bool btrans,
                        const float* A, int lda, long sAb, long sAh,
                        const float* Bm, int ldb, long sBb, long sBh,
                        float* C, int ldc, long sCb, long sCh,
                        const float* bias, int M, int N, int K,
                        float alpha, int Z, int Hdiv)
{
    dim3 grid(N / 64, M / 128, Z);
    if (btrans)
        hgemm_kernel<1><<<grid, 256>>>(A, lda, sAb, sAh, Bm, ldb, sBb, sBh,
                                       C, ldc, sCb, sCh, bias, M, N, K, alpha, Hdiv);
    else
        hgemm_kernel<0><<<grid, 256>>>(A, lda, sAb, sAh, Bm, ldb, sBb, sBh,
                                       C, ldc, sCb, sCh, bias, M, N, K, alpha, Hdiv);
}

extern "C" void kernel_launch(void* const* d_in, const int* in_sizes, int n_in,
                              void* d_out, int out_size)
{
    const float* queries = (const float*)d_in[0];
    const float* keys    = (const float*)d_in[1];
    const int*   q_len   = (const int*)  d_in[2];
    const float* cWq = (const float*)d_in[3];  const float* cbq = (const float*)d_in[4];
    const float* cWk = (const float*)d_in[5];  const float* cbk = (const float*)d_in[6];
    const float* cWv = (const float*)d_in[7];  const float* cbv = (const float*)d_in[8];
    const float* cWo = (const float*)d_in[9];  const float* cbo = (const float*)d_in[10];
    const float* sWq = (const float*)d_in[11]; const float* sbq = (const float*)d_in[12];
    const float* sWk = (const float*)d_in[13]; const float* sbk = (const float*)d_in[14];
    const float* sWv = (const float*)d_in[15]; const float* sbv = (const float*)d_in[16];
    const float* sWo = (const float*)d_in[17]; const float* sbo = (const float*)d_in[18];
    const float* Wf  = (const float*)d_in[19]; const float* bf  = (const float*)d_in[20];
    const float* g_cross = (const float*)d_in[21]; const float* b_cross = (const float*)d_in[22];
    const float* g_ffn   = (const float*)d_in[23]; const float* b_ffn   = (const float*)d_in[24];
    const float* g_self  = (const float*)d_in[25]; const float* b_self  = (const float*)d_in[26];

    float* out_q = (float*)d_out;
    float* out_w = out_q + (size_t)PB * PLQ * PHID;

    float *S, *QM, *Qp, *Kp, *Vp, *Op, *Pp, *X1, *Fb, *X2;
    cudaGetSymbolAddress((void**)&S,  g_S);
    cudaGetSymbolAddress((void**)&QM, g_QM);
    cudaGetSymbolAddress((void**)&Qp, g_Qp);
    cudaGetSymbolAddress((void**)&Kp, g_Kp);
    cudaGetSymbolAddress((void**)&Vp, g_Vp);
    cudaGetSymbolAddress((void**)&Op, g_Op);
    cudaGetSymbolAddress((void**)&Pp, g_Pp);
    cudaGetSymbolAddress((void**)&X1, g_X1);
    cudaGetSymbolAddress((void**)&Fb, g_Fb);
    cudaGetSymbolAddress((void**)&X2, g_X2);

    const int MQ = PB * PLQ;   // 4096
    const int MK = PB * PLK;   // 8192
    const long sQb = (long)PLQ * PE, sKb = (long)PLK * PE;
    const long sScrC = (long)PH * PLQ * PLK, sScrH = (long)PLQ * PLK;   // cross scores
    const long sSsC  = (long)PH * PLQ * PLQ, sSsH  = (long)PLQ * PLQ;   // self scores
    const float scale = 0.125f;  // 1/sqrt(64)

    // 1) masked queries
    mask_rows_kernel<<<MQ, 128>>>(queries, QM, q_len);

    // 2) cross projections
    launch_gemm(true, QM,   PE, 0,0, cWq, PE, 0,0, Qp, PE, 0,0, cbq, MQ, PE, PE, 1.f, 1, 1);
    launch_gemm(true, keys, PE, 0,0, cWk, PE, 0,0, Kp, PE, 0,0, cbk, MK, PE, PE, 1.f, 1, 1);
    launch_gemm(true, keys, PE, 0,0, cWv, PE, 0,0, Vp, PE, 0,0, cbv, MK, PE, PE, 1.f, 1, 1);

    // 3) cross scores S[b,h,q,k] = scale * Q·K   (Z = B*H)
    launch_gemm(true, Qp, PE, sQb, PHD, Kp, PE, sKb, PHD,
                S, PLK, sScrC, sScrH, nullptr, PLQ, PLK, PHD, scale, PB * PH, PH);

    // 4) softmax over LK (no key mask in cross)
    softmax_kernel<<<PB * PH * PLQ, 256>>>(S, PLK, 0, q_len, PH * PLQ);

    // 5) weights output (mean over heads, invalid q rows -> 0)
    weights_kernel<<<MQ, 256>>>(S, q_len, out_w);

    // 6) O = W @ V  (B as [K,N]: V rows are keys)
    launch_gemm(false, S, PLK, sScrC, sScrH, Vp, PE, sKb, PHD,
                Op, PE, sQb, PHD, nullptr, PLQ, PHD, PLK, 1.f, PB * PH, PH);

    // 7) cross out-projection
    launch_gemm(true, Op, PE, 0,0, cWo, PE, 0,0, Pp, PE, 0,0, cbo, MQ, PE, PE, 1.f, 1, 1);

    // 8) x1 = LN(silu(cross + qm))
    add_silu_ln_kernel<<<MQ, 128>>>(Pp, QM, g_cross, b_cross, X1, q_len, 0);

    // 9) FFN + LN
    launch_gemm(true, X1, PE, 0,0, Wf, PE, 0,0, Fb, PHID, 0,0, bf, MQ, PHID, PE, 1.f, 1, 1);
    add_silu_ln_kernel<<<MQ, 128>>>(X1, Fb, g_ffn, b_ffn, X2, q_len, 0);

    // 10) self projections
    launch_gemm(true, X2, PHID, 0,0, sWq, PHID, 0,0, Qp, PHID, 0,0, sbq, MQ, PHID, PHID, 1.f, 1, 1);
    launch_gemm(true, X2, PHID, 0,0, sWk, PHID, 0,0, Kp, PHID, 0,0, sbk, MQ, PHID, PHID, 1.f, 1, 1);
    launch_gemm(true, X2, PHID, 0,0, sWv, PHID, 0,0, Vp, PHID, 0,0, sbv, MQ, PHID, PHID, 1.f, 1, 1);

    // 11) self scores (Z = B*H)
    launch_gemm(true, Qp, PHID, sQb, PHD, Kp, PHID, sQb, PHD,
                S, PLQ, sSsC, sSsH, nullptr, PLQ, PLQ, PHD, scale, PB * PH, PH);

    // 12) masked softmax over LQ: only k < q_len[b] participate
    softmax_kernel<<<PB * PH * PLQ, 256>>>(S, PLQ, 1, q_len, PH * PLQ);

    // 13) O2 = W2 @ V
    launch_gemm(false, S, PLQ, sSsC, sSsH, Vp, PHID, sQb, PHD,
                Op, PHID, sQb, PHD, nullptr, PLQ, PHD, PLQ, 1.f, PB * PH, PH);

    // 14) self out-projection
    launch_gemm(true, Op, PHID, 0,0, sWo, PHID, 0,0, Pp, PHID, 0,0, sbo, MQ, PHID, PHID, 1.f, 1, 1);

    // 15) final: out = LN(silu(x2 + so)), invalid rows zeroed
    add_silu_ln_kernel<<<MQ, 128>>>(X2, Pp, g_self, b_self, out_q, q_len, 1);
}

// round 3
// speedup vs baseline: 2.9175x; 1.2300x over previous
#include <cuda_runtime.h>
#include <cuda_fp16.h>
#include <cstdint>
#include <cstddef>

// Problem constants
#define PB   4
#define PLQ  1024
#define PLK  2048
#define PE   512
#define PHID 512
#define PH   8
#define PHD  64

// ---------------------------------------------------------------------------
// Scratch (__device__ globals; no runtime allocation allowed)
// ---------------------------------------------------------------------------
__device__ float  g_S [(size_t)PB * PH * PLQ * PLK];   // fp32 scores (cross; reused for self)
__device__ __half g_P16[(size_t)PB * PH * PLQ * PLK];  // fp16 softmax probs
__device__ float  g_QM[PB * PLQ * PE];                 // masked queries fp32 (residual)
__device__ float  g_Pp[PB * PLQ * PE];                 // out-projection fp32
__device__ float  g_X1[PB * PLQ * PE];                 // after cross LN fp32
__device__ float  g_Fb[PB * PLQ * PHID];               // FFN fp32
__device__ float  g_X2[PB * PLQ * PHID];               // after FFN LN fp32

__device__ __half g_w16 [9 * PE * PE];                 // cWq,cWk,cWv,cWo,sWq,sWk,sWv,sWo,Wf
__device__ __half g_keys16[PB * PLK * PE];
__device__ __half g_QM16 [PB * PLQ * PE];
__device__ __half g_Qp16 [PB * PLQ * PE];
__device__ __half g_Kp16 [PB * PLK * PE];
__device__ __half g_Vp16 [PB * PLK * PE];
__device__ __half g_Op16 [PB * PLQ * PE];
__device__ __half g_X116 [PB * PLQ * PE];
__device__ __half g_X216 [PB * PLQ * PE];

// ---------------------------------------------------------------------------
// cp.async helpers
// ---------------------------------------------------------------------------
__device__ __forceinline__ void cpasync16(uint32_t dst, const void* src) {
    asm volatile("cp.async.cg.shared.global [%0], [%1], 16;" :: "r"(dst), "l"(src));
}
__device__ __forceinline__ void cpcommit() {
    asm volatile("cp.async.commit_group;");
}

// ---------------------------------------------------------------------------
// Pipelined tensor-core HGEMM (fp16 in, fp32 accum, fp32/fp16 out)
//   B_TRANS=1: B is [N,K] row-major  (C = A @ B^T)
//   B_TRANS=0: B is [K,N] row-major  (C = A @ B)
// Batched over blockIdx.z: off = (z/Hdiv)*s_b + (z%Hdiv)*s_h
// M%128==0, N%64==0, K%64==0. CTA tile 128x64x64, 8 warps 4x2, warp 32x32.
// 2-stage cp.async double buffer; XOR-swizzled smem; ldmatrix (+.trans for B_TRANS=0).
// ---------------------------------------------------------------------------
template<int B_TRANS>
__global__ __launch_bounds__(256)
void hgemm2_kernel(const __half* __restrict__ A, int lda, long sAb, long sAh,
                   const __half* __restrict__ Bm, int ldb, long sBb, long sBh,
                   float* __restrict__ C32, __half* __restrict__ C16,
                   int ldc, long sCb, long sCh,
                   const float* __restrict__ bias,
                   int M, int N, int K, float alpha, int Hdiv)
{
    const int z  = blockIdx.z;
    const int zb = z / Hdiv, zh = z % Hdiv;
    A  += (size_t)zb * sAb + (size_t)zh * sAh;
    Bm += (size_t)zb * sBb + (size_t)zh * sBh;

    constexpr int BM = 128, BN = 64, BK = 64;
    __shared__ __align__(16) __half sA[2][BM * BK];
    __shared__ __align__(16) __half sB[2][BN * BK];

    const int tid  = threadIdx.x;
    const int lane = tid & 31;
    const int warp = tid >> 5;
    const int wm   = warp & 3;
    const int wn   = warp >> 2;
    const int m0   = blockIdx.y * BM;
    const int n0   = blockIdx.x * BN;

    const uint32_t baseA[2] = { (uint32_t)__cvta_generic_to_shared(sA[0]),
                                (uint32_t)__cvta_generic_to_shared(sA[1]) };
    const uint32_t baseB[2] = { (uint32_t)__cvta_generic_to_shared(sB[0]),
                                (uint32_t)__cvta_generic_to_shared(sB[1]) };

    auto load_tile = [&](int stage, int k0) {
        // A: 128 rows x 8 chunks(16B) = 1024 chunks, 4 per thread
        #pragma unroll
        for (int i = 0; i < 4; i++) {
            int c  = tid + i * 256;
            int r  = c >> 3;
            int cc = c & 7;
            const void* src = A + (size_t)(m0 + r) * lda + k0 + cc * 8;
            uint32_t dst = baseA[stage] + (uint32_t)r * 128u + (uint32_t)((cc ^ (r & 7)) << 4);
            cpasync16(dst, src);
        }
        // B: 64 rows x 8 chunks = 512 chunks, 2 per thread
        #pragma unroll
        for (int i = 0; i < 2; i++) {
            int f  = tid + i * 256;
            int r  = f >> 3;
            int cc = f & 7;
            const void* src;
            if (B_TRANS) src = Bm + (size_t)(n0 + r) * ldb + k0 + cc * 8;  // rows = n
            else         src = Bm + (size_t)(k0 + r) * ldb + n0 + cc * 8;  // rows = k
            uint32_t dst = baseB[stage] + (uint32_t)r * 128u + (uint32_t)((cc ^ (r & 7)) << 4);
            cpasync16(dst, src);
        }
        cpcommit();
    };

    float d[2][4][4];
    #pragma unroll
    for (int mi = 0; mi < 2; mi++)
        #pragma unroll
        for (int ni = 0; ni < 4; ni++)
            #pragma unroll
            for (int j = 0; j < 4; j++) d[mi][ni][j] = 0.f;

    const int ntiles = K >> 6;
    load_tile(0, 0);

    for (int t = 0; t < ntiles; t++) {
        if (t + 1 < ntiles) {
            load_tile((t + 1) & 1, (t + 1) << 6);
            asm volatile("cp.async.wait_group 1;");
        } else {
            asm volatile("cp.async.wait_group 0;");
        }
        __syncthreads();

        const int st = t & 1;
        #pragma unroll
        for (int ks = 0; ks < 4; ks++) {
            const int kb = ks * 16;
            uint32_t a[2][4], b[4][2];
            #pragma unroll
            for (int mi = 0; mi < 2; mi++) {
                int r  = wm * 32 + mi * 16 + (lane & 15);
                int ck = kb + ((lane >> 4) << 3);
                uint32_t addr = baseA[st] + (uint32_t)r * 128u + (uint32_t)((((ck >> 3) ^ (r & 7))) << 4);
                asm volatile("ldmatrix.sync.aligned.m8n8.x4.shared.b16 {%0,%1,%2,%3}, [%4];"
                             : "=r"(a[mi][0]), "=r"(a[mi][1]), "=r"(a[mi][2]), "=r"(a[mi][3])
                             : "r"(addr));
            }
            #pragma unroll
            for (int ni = 0; ni < 4; ni++) {
                if (B_TRANS) {
                    int r  = wn * 32 + ni * 8 + (lane & 7);
                    int ck = kb + (((lane >> 3) & 1) << 3);
                    uint32_t addr = baseB[st] + (uint32_t)r * 128u + (uint32_t)((((ck >> 3) ^ (r & 7))) << 4);
                    asm volatile("ldmatrix.sync.aligned.m8n8.x2.shared.b16 {%0,%1}, [%2];"
                                 : "=r"(b[ni][0]), "=r"(b[ni][1])
                                 : "r"(addr));
                } else {
                    // smem holds [k][n]; .trans gives the k-major B fragment
                    int r  = kb + (lane & 15);                 // k row
                    int ck = (wn * 32 + ni * 8) >> 3;          // n chunk
                    uint32_t addr = baseB[st] + (uint32_t)r * 128u + (uint32_t)(((ck ^ (r & 7))) << 4);
                    asm volatile("ldmatrix.sync.aligned.m8n8.x2.trans.shared.b16 {%0,%1}, [%2];"
                                 : "=r"(b[ni][0]), "=r"(b[ni][1])
                                 : "r"(addr));
                }
            }
            #pragma unroll
            for (int mi = 0; mi < 2; mi++)
                #pragma unroll
                for (int ni = 0; ni < 4; ni++) {
                    asm volatile(
                        "mma.sync.aligned.m16n8k16.row.col.f32.f16.f16.f32 "
                        "{%0,%1,%2,%3}, {%4,%5,%6,%7}, {%8,%9}, {%0,%1,%2,%3};"
                        : "+f"(d[mi][ni][0]), "+f"(d[mi][ni][1]),
                          "+f"(d[mi][ni][2]), "+f"(d[mi][ni][3])
                        : "r"(a[mi][0]), "r"(a[mi][1]), "r"(a[mi][2]), "r"(a[mi][3]),
                          "r"(b[ni][0]), "r"(b[ni][1]));
                }
        }
        __syncthreads();
    }

    // ---- epilogue ----
    float*  Cf = C32 ? C32 + (size_t)zb * sCb + (size_t)zh * sCh : nullptr;
    __half* Ch = C16 ? C16 + (size_t)zb * sCb + (size_t)zh * sCh : nullptr;
    const int g = lane >> 2, tq = lane & 3;
    #pragma unroll
    for (int mi = 0; mi < 2; mi++) {
        #pragma unroll
        for (int ni = 0; ni < 4; ni++) {
            int rr = m0 + wm * 32 + mi * 16 + g;
            int cc = n0 + wn * 32 + ni * 8 + tq * 2;
            float b0 = 0.f, b1 = 0.f;
            if (bias) { b0 = bias[cc]; b1 = bias[cc + 1]; }
            float o00 = d[mi][ni][0] * alpha + b0, o01 = d[mi][ni][1] * alpha + b1;
            float o10 = d[mi][ni][2] * alpha + b0, o11 = d[mi][ni][3] * alpha + b1;
            if (Cf) {
                *reinterpret_cast<float2*>(Cf + (size_t)rr * ldc + cc)       = make_float2(o00, o01);
                *reinterpret_cast<float2*>(Cf + (size_t)(rr + 8) * ldc + cc) = make_float2(o10, o11);
            }
            if (Ch) {
                *reinterpret_cast<__half2*>(Ch + (size_t)rr * ldc + cc)       = __floats2half2_rn(o00, o01);
                *reinterpret_cast<__half2*>(Ch + (size_t)(rr + 8) * ldc + cc) = __floats2half2_rn(o10, o11);
            }
        }
    }
}

// ---------------------------------------------------------------------------
// fp32 -> fp16 convert (n % 4 == 0)
// ---------------------------------------------------------------------------
__global__ void f32_to_f16_kernel(const float* __restrict__ in, __half* __restrict__ out, int n)
{
    int i = (blockIdx.x * blockDim.x + threadIdx.x) * 4;
    if (i >= n) return;
    float4 v = *reinterpret_cast<const float4*>(in + i);
    __half2* o = reinterpret_cast<__half2*>(out + i);
    o[0] = __floats2half2_rn(v.x, v.y);
    o[1] = __floats2half2_rn(v.z, v.w);
}

// ---------------------------------------------------------------------------
// Mask invalid query rows: out32/out16[r,:] = valid ? in : 0
// ---------------------------------------------------------------------------
__global__ void mask_rows_kernel(const float* __restrict__ in, float* __restrict__ out32,
                                 __half* __restrict__ out16, const int* __restrict__ q_len)
{
    int r = blockIdx.x;
    bool valid = (r % PLQ) < q_len[r / PLQ];
    const float4* src = reinterpret_cast<const float4*>(in + (size_t)r * PE);
    float4* dst = reinterpret_cast<float4*>(out32 + (size_t)r * PE);
    __half2* dh = reinterpret_cast<__half2*>(out16 + (size_t)r * PE);
    for (int c = threadIdx.x; c < PE / 4; c += blockDim.x) {
        float4 v = valid ? src[c] : make_float4(0.f, 0.f, 0.f, 0.f);
        dst[c] = v;
        dh[c * 2]     = __floats2half2_rn(v.x, v.y);
        dh[c * 2 + 1] = __floats2half2_rn(v.z, v.w);
    }
}

// ---------------------------------------------------------------------------
// Single-pass register softmax. rowlen in {1024, 2048}. Writes fp32 (S) and
// fp16 (P). Masked: only k < q_len participate; tail -> 0.
// ---------------------------------------------------------------------------
__global__ __launch_bounds__(256)
void softmax2_kernel(float* __restrict__ S, __half* __restrict__ P,
                     int rowlen, int masked,
                     const int* __restrict__ q_len, int rows_per_b)
{
    int r = blockIdx.x, tid = threadIdx.x;
    float* row = S + (size_t)r * rowlen;
    __half* prow = P + (size_t)r * rowlen;
    int limit = masked ? q_len[r / rows_per_b] : rowlen;
    const int nch = rowlen >> 8;   // 4 or 8

    float v[8];
    float mx = -3.4e38f;
    #pragma unroll
    for (int i = 0; i < 8; i++) {
        if (i < nch) {
            int k = tid + (i << 8);
            v[i] = (k < limit) ? row[k] : -3.4e38f;
            mx = fmaxf(mx, v[i]);
        }
    }
    #pragma unroll
    for (int o = 16; o > 0; o >>= 1) mx = fmaxf(mx, __shfl_xor_sync(0xffffffffu, mx, o));
    __shared__ float sm1[8], sm2[8];
    if ((tid & 31) == 0) sm1[tid >> 5] = mx;
    __syncthreads();
    #pragma unroll
    for (int j = 0; j < 8; j++) mx = fmaxf(mx, sm1[j]);

    float sum = 0.f;
    #pragma unroll
    for (int i = 0; i < 8; i++) {
        if (i < nch) {
            v[i] = __expf(v[i] - mx);   // masked lanes underflow to 0
            sum += v[i];
        }
    }
    #pragma unroll
    for (int o = 16; o > 0; o >>= 1) sum += __shfl_xor_sync(0xffffffffu, sum, o);
    if ((tid & 31) == 0) sm2[tid >> 5] = sum;
    __syncthreads();
    sum = 0.f;
    #pragma unroll
    for (int j = 0; j < 8; j++) sum += sm2[j];
    float inv = 1.0f / sum;

    #pragma unroll
    for (int i = 0; i < 8; i++) {
        if (i < nch) {
            int k = tid + (i << 8);
            float w = v[i] * inv;
            row[k] = w;
            prow[k] = __float2half(w);
        }
    }
}

// ---------------------------------------------------------------------------
// weights output: wout[b,q,k] = valid(q) ? mean_h S[(b*H+h),q,k] : 0
// ---------------------------------------------------------------------------
__global__ __launch_bounds__(256)
void weights_kernel(const float* __restrict__ S, const int* __restrict__ q_len,
                    float* __restrict__ wout)
{
    int r = blockIdx.x;
    int b = r / PLQ, q = r % PLQ;
    float* out = wout + (size_t)r * PLK;
    if (q >= q_len[b]) {
        for (int k = threadIdx.x; k < PLK; k += 256) out[k] = 0.f;
        return;
    }
    const float* base = S + ((size_t)b * PH) * PLQ * PLK + (size_t)q * PLK;
    for (int k = threadIdx.x; k < PLK; k += 256) {
        float s = 0.f;
        #pragma unroll
        for (int h = 0; h < PH; h++) s += base[(size_t)h * PLQ * PLK + k];
        out[k] = s * (1.0f / PH);
    }
}

// ---------------------------------------------------------------------------
// out[r,:] = LN( silu(X + Y) )*g + b ; optional fp16 copy; optional zero rows
// ---------------------------------------------------------------------------
__global__ __launch_bounds__(128)
void add_silu_ln_kernel(const float* __restrict__ X, const float* __restrict__ Y,
                        const float* __restrict__ g, const float* __restrict__ bln,
                        float* __restrict__ out, __half* __restrict__ out16,
                        const int* __restrict__ q_len, int zero_invalid)
{
    constexpr int D = 512;
    int r = blockIdx.x;
    int tid = threadIdx.x;
    int c = tid * 4;

    float4 x = *reinterpret_cast<const float4*>(X + (size_t)r * D + c);
    float4 y = *reinterpret_cast<const float4*>(Y + (size_t)r * D + c);
    float v[4] = {x.x + y.x, x.y + y.y, x.z + y.z, x.w + y.w};

    float s[4], sum = 0.f, sumsq = 0.f;
    #pragma unroll
    for (int i = 0; i < 4; i++) {
        s[i] = v[i] / (1.0f + __expf(-v[i]));
        sum += s[i];
        sumsq += s[i] * s[i];
    }

    __shared__ float r1[128], r2[128];
    r1[tid] = sum; r2[tid] = sumsq; __syncthreads();
    for (int st = 64; st > 0; st >>= 1) {
        if (tid < st) { r1[tid] += r1[tid + st]; r2[tid] += r2[tid + st]; }
        __syncthreads();
    }
    float mu  = r1[0] * (1.0f / D);
    float var = r2[0] * (1.0f / D) - mu * mu;
    float rs  = rsqrtf(var + 1e-5f);

    bool zero = zero_invalid && ((r % PLQ) >= q_len[r / PLQ]);

    float4 gg = *reinterpret_cast<const float4*>(g + c);
    float4 bb = *reinterpret_cast<const float4*>(bln + c);
    float4 o;
    o.x = zero ? 0.f : (s[0] - mu) * rs * gg.x + bb.x;
    o.y = zero ? 0.f : (s[1] - mu) * rs * gg.y + bb.y;
    o.z = zero ? 0.f : (s[2] - mu) * rs * gg.z + bb.z;
    o.w = zero ? 0.f : (s[3] - mu) * rs * gg.w + bb.w;
    *reinterpret_cast<float4*>(out + (size_t)r * D + c) = o;
    if (out16) {
        __half2* oh = reinterpret_cast<__half2*>(out16 + (size_t)r * D + c);
        oh[0] = __floats2half2_rn(o.x, o.y);
        oh[1] = __floats2half2_rn(o.z, o.w);
    }
}

// ---------------------------------------------------------------------------
// Host launcher
// ---------------------------------------------------------------------------
static void launch_gemm(bool btrans,
                        const __half* A, int lda, long sAb, long sAh,
                        const __half* Bm, int ldb, long sBb, long sBh,
                        float* C32, __half* C16, int ldc, long sCb, long sCh,
                        const float* bias, int M, int N, int K,
                        float alpha, int Z, int Hdiv)
{
    dim3 grid(N / 64, M / 128, Z);
    if (btrans)
        hgemm2_kernel<1><<<grid, 256>>>(A, lda, sAb, sAh, Bm, ldb, sBb, sBh,
                                        C32, C16, ldc, sCb, sCh, bias, M, N, K, alpha, Hdiv);
    else
        hgemm2_kernel<0><<<grid, 256>>>(A, lda, sAb, sAh, Bm, ldb, sBb, sBh,
                                        C32, C16, ldc, sCb, sCh, bias, M, N, K, alpha, Hdiv);
}

extern "C" void kernel_launch(void* const* d_in, const int* in_sizes, int n_in,
                              void* d_out, int out_size)
{
    const float* queries = (const float*)d_in[0];
    const float* keys    = (const float*)d_in[1];
    const int*   q_len   = (const int*)  d_in[2];
    const float* cWq = (const float*)d_in[3];  const float* cbq = (const float*)d_in[4];
    const float* cWk = (const float*)d_in[5];  const float* cbk = (const float*)d_in[6];
    const float* cWv = (const float*)d_in[7];  const float* cbv = (const float*)d_in[8];
    const float* cWo = (const float*)d_in[9];  const float* cbo = (const float*)d_in[10];
    const float* sWq = (const float*)d_in[11]; const float* sbq = (const float*)d_in[12];
    const float* sWk = (const float*)d_in[13]; const float* sbk = (const float*)d_in[14];
    const float* sWv = (const float*)d_in[15]; const float* sbv = (const float*)d_in[16];
    const float* sWo = (const float*)d_in[17]; const float* sbo = (const float*)d_in[18];
    const float* Wf  = (const float*)d_in[19]; const float* bf  = (const float*)d_in[20];
    const float* g_cross = (const float*)d_in[21]; const float* b_cross = (const float*)d_in[22];
    const float* g_ffn   = (const float*)d_in[23]; const float* b_ffn   = (const float*)d_in[24];
    const float* g_self  = (const float*)d_in[25]; const float* b_self  = (const float*)d_in[26];

    float* out_q = (float*)d_out;
    float* out_w = out_q + (size_t)PB * PLQ * PHID;

    float *S, *QM, *Pp, *X1, *Fb, *X2;
    __half *P16, *w16, *keys16, *QM16, *Qp16, *Kp16, *Vp16, *Op16, *X116, *X216;
    cudaGetSymbolAddress((void**)&S,    g_S);
    cudaGetSymbolAddress((void**)&P16,  g_P16);
    cudaGetSymbolAddress((void**)&QM,   g_QM);
    cudaGetSymbolAddress((void**)&Pp,   g_Pp);
    cudaGetSymbolAddress((void**)&X1,   g_X1);
    cudaGetSymbolAddress((void**)&Fb,   g_Fb);
    cudaGetSymbolAddress((void**)&X2,   g_X2);
    cudaGetSymbolAddress((void**)&w16,  g_w16);
    cudaGetSymbolAddress((void**)&keys16, g_keys16);
    cudaGetSymbolAddress((void**)&QM16, g_QM16);
    cudaGetSymbolAddress((void**)&Qp16, g_Qp16);
    cudaGetSymbolAddress((void**)&Kp16, g_Kp16);
    cudaGetSymbolAddress((void**)&Vp16, g_Vp16);
    cudaGetSymbolAddress((void**)&Op16, g_Op16);
    cudaGetSymbolAddress((void**)&X116, g_X116);
    cudaGetSymbolAddress((void**)&X216, g_X216);

    const int MQ = PB * PLQ;   // 4096
    const int MK = PB * PLK;   // 8192
    const long sQb = (long)PLQ * PE, sKb = (long)PLK * PE;
    const long sScrC = (long)PH * PLQ * PLK, sScrH = (long)PLQ * PLK;   // cross scores
    const long sSsC  = (long)PH * PLQ * PLQ, sSsH  = (long)PLQ * PLQ;   // self scores
    const float scale = 0.125f;  // 1/sqrt(64)

    // 0) convert weights + keys to fp16
    const float* Ws[9] = {cWq, cWk, cWv, cWo, sWq, sWk, sWv, sWo, Wf};
    for (int i = 0; i < 9; i++)
        f32_to_f16_kernel<<<(PE * PE) / 1024, 256>>>(Ws[i], w16 + (size_t)i * PE * PE, PE * PE);
    f32_to_f16_kernel<<<(MK * PE) / 1024, 256>>>(keys, keys16, MK * PE);

    // 1) masked queries (fp32 + fp16)
    mask_rows_kernel<<<MQ, 128>>>(queries, QM, QM16, q_len);

    // 2) cross projections (fp16 out)
    launch_gemm(true, QM16,   PE, 0,0, w16 + 0*PE*PE, PE, 0,0, nullptr, Qp16, PE, 0,0, cbq, MQ, PE, PE, 1.f, 1, 1);
    launch_gemm(true, keys16, PE, 0,0, w16 + 1*PE*PE, PE, 0,0, nullptr, Kp16, PE, 0,0, cbk, MK, PE, PE, 1.f, 1, 1);
    launch_gemm(true, keys16, PE, 0,0, w16 + 2*PE*PE, PE, 0,0, nullptr, Vp16, PE, 0,0, cbv, MK, PE, PE, 1.f, 1, 1);

    // 3) cross scores S[b,h,q,k] (fp32)
    launch_gemm(true, Qp16, PE, sQb, PHD, Kp16, PE, sKb, PHD,
                S, nullptr, PLK, sScrC, sScrH, nullptr, PLQ, PLK, PHD, scale, PB * PH, PH);

    // 4) softmax over LK -> S (fp32) + P16
    softmax2_kernel<<<PB * PH * PLQ, 256>>>(S, P16, PLK, 0, q_len, PH * PLQ);

    // 5) weights output (mean over heads from fp32 S)
    weights_kernel<<<MQ, 256>>>(S, q_len, out_w);

    // 6) O = P @ V  (fp16 x fp16 -> fp16)
    launch_gemm(false, P16, PLK, sScrC, sScrH, Vp16, PE, sKb, PHD,
                nullptr, Op16, PE, sQb, PHD, nullptr, PLQ, PHD, PLK, 1.f, PB * PH, PH);

    // 7) cross out-projection (fp32)
    launch_gemm(true, Op16, PE, 0,0, w16 + 3*PE*PE, PE, 0,0, Pp, nullptr, PE, 0,0, cbo, MQ, PE, PE, 1.f, 1, 1);

    // 8) x1 = LN(silu(cross + qm))  (fp32 + fp16)
    add_silu_ln_kernel<<<MQ, 128>>>(Pp, QM, g_cross, b_cross, X1, X116, q_len, 0);

    // 9) FFN + LN
    launch_gemm(true, X116, PE, 0,0, w16 + 8*PE*PE, PE, 0,0, Fb, nullptr, PHID, 0,0, bf, MQ, PHID, PE, 1.f, 1, 1);
    add_silu_ln_kernel<<<MQ, 128>>>(X1, Fb, g_ffn, b_ffn, X2, X216, q_len, 0);

    // 10) self projections (fp16)
    launch_gemm(true, X216, PHID, 0,0, w16 + 4*PE*PE, PHID, 0,0, nullptr, Qp16, PHID, 0,0, sbq, MQ, PHID, PHID, 1.f, 1, 1);
    launch_gemm(true, X216, PHID, 0,0, w16 + 5*PE*PE, PHID, 0,0, nullptr, Kp16, PHID, 0,0, sbk, MQ, PHID, PHID, 1.f, 1, 1);
    launch_gemm(true, X216, PHID, 0,0, w16 + 6*PE*PE, PHID, 0,0, nullptr, Vp16, PHID, 0,0, sbv, MQ, PHID, PHID, 1.f, 1, 1);

    // 11) self scores (fp32)
    launch_gemm(true, Qp16, PHID, sQb, PHD, Kp16, PHID, sQb, PHD,
                S, nullptr, PLQ, sSsC, sSsH, nullptr, PLQ, PLQ, PHD, scale, PB * PH, PH);

    // 12) masked softmax over LQ -> S + P16
    softmax2_kernel<<<PB * PH * PLQ, 256>>>(S, P16, PLQ, 1, q_len, PH * PLQ);

    // 13) O2 = P @ V
    launch_gemm(false, P16, PLQ, sSsC, sSsH, Vp16, PHID, sQb, PHD,
                nullptr, Op16, PHID, sQb, PHD, nullptr, PLQ, PHD, PLQ, 1.f, PB * PH, PH);

    // 14) self out-projection (fp32)
    launch_gemm(true, Op16, PHID, 0,0, w16 + 7*PE*PE, PHID, 0,0, Pp, nullptr, PHID, 0,0, sbo, MQ, PHID, PHID, 1.f, 1, 1);

    // 15) final: out = LN(silu(x2 + so)), invalid rows zeroed
    add_silu_ln_kernel<<<MQ, 128>>>(X2, Pp, g_self, b_self, out_q, nullptr, q_len, 1);
}

// round 4
// speedup vs baseline: 3.1113x; 1.0664x over previous
#include <cuda_runtime.h>
#include <cuda_fp16.h>
#include <cstdint>
#include <cstddef>

// Problem constants
#define PB   4
#define PLQ  1024
#define PLK  2048
#define PE   512
#define PHID 512
#define PH   8
#define PHD  64

// ---------------------------------------------------------------------------
// Scratch (__device__ globals; no runtime allocation allowed)
// ---------------------------------------------------------------------------
__device__ float  g_QM[PB * PLQ * PE];                 // masked queries fp32 (residual)
__device__ float  g_Pp[PB * PLQ * PE];                 // out-projection fp32
__device__ float  g_X1[PB * PLQ * PE];                 // after cross LN fp32
__device__ float  g_Fb[PB * PLQ * PHID];               // FFN fp32
__device__ float  g_X2[PB * PLQ * PHID];               // after FFN LN fp32

__device__ __half g_w16 [9 * PE * PE];                 // cWq,cWk,cWv,cWo,sWq,sWk,sWv,sWo,Wf
__device__ __half g_keys16[PB * PLK * PE];
__device__ __half g_QM16 [PB * PLQ * PE];
__device__ __half g_Qp16 [PB * PLK * PE];
__device__ __half g_Kp16 [PB * PLK * PE];
__device__ __half g_Vp16 [PB * PLK * PE];
__device__ __half g_Op16 [PB * PLQ * PE];
__device__ __half g_X116 [PB * PLQ * PE];
__device__ __half g_X216 [PB * PLQ * PE];

__device__ float  g_sm[PB * PH * PLQ];                 // cross softmax row max (scaled)
__device__ float  g_sl[PB * PH * PLQ];                 // cross softmax row sum

// ---------------------------------------------------------------------------
// cp.async helpers
// ---------------------------------------------------------------------------
__device__ __forceinline__ void cpasync16(uint32_t dst, const void* src) {
    asm volatile("cp.async.cg.shared.global [%0], [%1], 16;" :: "r"(dst), "l"(src));
}
__device__ __forceinline__ void cpcommit() {
    asm volatile("cp.async.commit_group;");
}

// ---------------------------------------------------------------------------
// Pipelined tensor-core HGEMM (fp16 in, fp32 accum, fp32/fp16 out)
//   B_TRANS=1: B is [N,K] row-major  (C = A @ B^T)
// CTA tile 128x64x64, 8 warps 4x2, warp 32x32, 2-stage cp.async.
// ---------------------------------------------------------------------------
template<int B_TRANS>
__global__ __launch_bounds__(256)
void hgemm2_kernel(const __half* __restrict__ A, int lda, long sAb, long sAh,
                   const __half* __restrict__ Bm, int ldb, long sBb, long sBh,
                   float* __restrict__ C32, __half* __restrict__ C16,
                   int ldc, long sCb, long sCh,
                   const float* __restrict__ bias,
                   int M, int N, int K, float alpha, int Hdiv)
{
    const int z  = blockIdx.z;
    const int zb = z / Hdiv, zh = z % Hdiv;
    A  += (size_t)zb * sAb + (size_t)zh * sAh;
    Bm += (size_t)zb * sBb + (size_t)zh * sBh;

    constexpr int BM = 128, BN = 64, BK = 64;
    __shared__ __align__(16) __half sA[2][BM * BK];
    __shared__ __align__(16) __half sB[2][BN * BK];

    const int tid  = threadIdx.x;
    const int lane = tid & 31;
    const int warp = tid >> 5;
    const int wm   = warp & 3;
    const int wn   = warp >> 2;
    const int m0   = blockIdx.y * BM;
    const int n0   = blockIdx.x * BN;

    const uint32_t baseA[2] = { (uint32_t)__cvta_generic_to_shared(sA[0]),
                                (uint32_t)__cvta_generic_to_shared(sA[1]) };
    const uint32_t baseB[2] = { (uint32_t)__cvta_generic_to_shared(sB[0]),
                                (uint32_t)__cvta_generic_to_shared(sB[1]) };

    auto load_tile = [&](int stage, int k0) {
        #pragma unroll
        for (int i = 0; i < 4; i++) {
            int c  = tid + i * 256;
            int r  = c >> 3;
            int cc = c & 7;
            const void* src = A + (size_t)(m0 + r) * lda + k0 + cc * 8;
            uint32_t dst = baseA[stage] + (uint32_t)r * 128u + (uint32_t)((cc ^ (r & 7)) << 4);
            cpasync16(dst, src);
        }
        #pragma unroll
        for (int i = 0; i < 2; i++) {
            int f  = tid + i * 256;
            int r  = f >> 3;
            int cc = f & 7;
            const void* src = Bm + (size_t)(n0 + r) * ldb + k0 + cc * 8;
            uint32_t dst = baseB[stage] + (uint32_t)r * 128u + (uint32_t)((cc ^ (r & 7)) << 4);
            cpasync16(dst, src);
        }
        cpcommit();
    };

    float d[2][4][4];
    #pragma unroll
    for (int mi = 0; mi < 2; mi++)
        #pragma unroll
        for (int ni = 0; ni < 4; ni++)
            #pragma unroll
            for (int j = 0; j < 4; j++) d[mi][ni][j] = 0.f;

    const int ntiles = K >> 6;
    load_tile(0, 0);

    for (int t = 0; t < ntiles; t++) {
        if (t + 1 < ntiles) {
            load_tile((t + 1) & 1, (t + 1) << 6);
            asm volatile("cp.async.wait_group 1;");
        } else {
            asm volatile("cp.async.wait_group 0;");
        }
        __syncthreads();

        const int st = t & 1;
        #pragma unroll
        for (int ks = 0; ks < 4; ks++) {
            const int kb = ks * 16;
            uint32_t a[2][4], b[4][2];
            #pragma unroll
            for (int mi = 0; mi < 2; mi++) {
                int r  = wm * 32 + mi * 16 + (lane & 15);
                int ck = kb + ((lane >> 4) << 3);
                uint32_t addr = baseA[st] + (uint32_t)r * 128u + (uint32_t)((((ck >> 3) ^ (r & 7))) << 4);
                asm volatile("ldmatrix.sync.aligned.m8n8.x4.shared.b16 {%0,%1,%2,%3}, [%4];"
                             : "=r"(a[mi][0]), "=r"(a[mi][1]), "=r"(a[mi][2]), "=r"(a[mi][3])
                             : "r"(addr));
            }
            #pragma unroll
            for (int ni = 0; ni < 4; ni++) {
                int r  = wn * 32 + ni * 8 + (lane & 7);
                int ck = kb + (((lane >> 3) & 1) << 3);
                uint32_t addr = baseB[st] + (uint32_t)r * 128u + (uint32_t)((((ck >> 3) ^ (r & 7))) << 4);
                asm volatile("ldmatrix.sync.aligned.m8n8.x2.shared.b16 {%0,%1}, [%2];"
                             : "=r"(b[ni][0]), "=r"(b[ni][1])
                             : "r"(addr));
            }
            #pragma unroll
            for (int mi = 0; mi < 2; mi++)
                #pragma unroll
                for (int ni = 0; ni < 4; ni++) {
                    asm volatile(
                        "mma.sync.aligned.m16n8k16.row.col.f32.f16.f16.f32 "
                        "{%0,%1,%2,%3}, {%4,%5,%6,%7}, {%8,%9}, {%0,%1,%2,%3};"
                        : "+f"(d[mi][ni][0]), "+f"(d[mi][ni][1]),
                          "+f"(d[mi][ni][2]), "+f"(d[mi][ni][3])
                        : "r"(a[mi][0]), "r"(a[mi][1]), "r"(a[mi][2]), "r"(a[mi][3]),
                          "r"(b[ni][0]), "r"(b[ni][1]));
                }
        }
        __syncthreads();
    }

    float*  Cf = C32 ? C32 + (size_t)zb * sCb + (size_t)zh * sCh : nullptr;
    __half* Ch = C16 ? C16 + (size_t)zb * sCb + (size_t)zh * sCh : nullptr;
    const int g = lane >> 2, tq = lane & 3;
    #pragma unroll
    for (int mi = 0; mi < 2; mi++) {
        #pragma unroll
        for (int ni = 0; ni < 4; ni++) {
            int rr = m0 + wm * 32 + mi * 16 + g;
            int cc = n0 + wn * 32 + ni * 8 + tq * 2;
            float b0 = 0.f, b1 = 0.f;
            if (bias) { b0 = bias[cc]; b1 = bias[cc + 1]; }
            float o00 = d[mi][ni][0] * alpha + b0, o01 = d[mi][ni][1] * alpha + b1;
            float o10 = d[mi][ni][2] * alpha + b0, o11 = d[mi][ni][3] * alpha + b1;
            if (Cf) {
                *reinterpret_cast<float2*>(Cf + (size_t)rr * ldc + cc)       = make_float2(o00, o01);
                *reinterpret_cast<float2*>(Cf + (size_t)(rr + 8) * ldc + cc) = make_float2(o10, o11);
            }
            if (Ch) {
                *reinterpret_cast<__half2*>(Ch + (size_t)rr * ldc + cc)       = __floats2half2_rn(o00, o01);
                *reinterpret_cast<__half2*>(Ch + (size_t)(rr + 8) * ldc + cc) = __floats2half2_rn(o10, o11);
            }
        }
    }
}

// ---------------------------------------------------------------------------
// Fused flash attention: per CTA one (b, h, 64-row q-tile).
// Online softmax with running (m, l); O accumulated in regs with rescale.
// Writes O (fp16, head-sliced [*,E] layout) and optional per-row stats (m,l).
// Scores scaled by 0.125 (1/sqrt(64)) inside softmax.
// masked=1: only keys k < q_len[b] participate.
// Dynamic smem layout (bytes):
//   sQ 0..8192 | sK 8192..24576 (2 stg) | sV 24576..40960 (2 stg)
//   sS 40960..57344 (f32 64x64) | sP 57344..65536 (f16 64x64)
//   sM 65536 | sL 65792 | sF 66048 | total 66304
// ---------------------------------------------------------------------------
__global__ __launch_bounds__(256)
void flash_kernel(const __half* __restrict__ Q, const __half* __restrict__ K,
                  const __half* __restrict__ V, __half* __restrict__ O,
                  float* __restrict__ stats_m, float* __restrict__ stats_l,
                  int LK, int masked, const int* __restrict__ q_len)
{
    extern __shared__ char smem[];
    __half* sQ = reinterpret_cast<__half*>(smem);
    float*  sS = reinterpret_cast<float*>(smem + 40960);
    float*  sM = reinterpret_cast<float*>(smem + 65536);
    float*  sL = reinterpret_cast<float*>(smem + 65792);
    float*  sF = reinterpret_cast<float*>(smem + 66048);

    const int b = blockIdx.z, h = blockIdx.y, q0 = blockIdx.x * 64;
    const int tid = threadIdx.x, lane = tid & 31, warp = tid >> 5;
    const int wm = warp & 3, wn = warp >> 2;

    const int limit = masked ? q_len[b] : LK;
    const int nt = (limit + 63) >> 6;

    const __half* Qb = Q + ((size_t)b * PLQ + q0) * PE + h * PHD;
    const __half* Kb = K + ((size_t)b * LK) * PE + h * PHD;
    const __half* Vb = V + ((size_t)b * LK) * PE + h * PHD;

    const uint32_t baseQ = (uint32_t)__cvta_generic_to_shared(smem);
    const uint32_t baseK = baseQ + 8192;
    const uint32_t baseV = baseQ + 24576;
    const uint32_t baseP = baseQ + 57344;

    if (tid < 64) { sM[tid] = -3.0e38f; sL[tid] = 0.f; }

    // Q tile: 64 rows x 8 chunks = 512, 2/thread
    #pragma unroll
    for (int i = 0; i < 2; i++) {
        int f = tid + i * 256;
        int r = f >> 3, c = f & 7;
        cpasync16(baseQ + (uint32_t)r * 128u + (uint32_t)((c ^ (r & 7)) << 4),
                  Qb + (size_t)r * PE + c * 8);
    }
    cpcommit();

    auto loadKV = [&](int stage, int k0) {
        #pragma unroll
        for (int i = 0; i < 2; i++) {
            int f = tid + i * 256;
            int r = f >> 3, c = f & 7;
            cpasync16(baseK + stage * 8192u + (uint32_t)r * 128u + (uint32_t)((c ^ (r & 7)) << 4),
                      Kb + (size_t)(k0 + r) * PE + c * 8);
        }
        #pragma unroll
        for (int i = 0; i < 2; i++) {
            int f = tid + i * 256;
            int r = f >> 3, c = f & 7;
            cpasync16(baseV + stage * 8192u + (uint32_t)r * 128u + (uint32_t)((c ^ (r & 7)) << 4),
                      Vb + (size_t)(k0 + r) * PE + c * 8);
        }
        cpcommit();
    };
    loadKV(0, 0);

    float o[4][4];
    #pragma unroll
    for (int ni = 0; ni < 4; ni++)
        #pragma unroll
        for (int j = 0; j < 4; j++) o[ni][j] = 0.f;

    for (int t = 0; t < nt; t++) {
        if (t + 1 < nt) {
            loadKV((t + 1) & 1, (t + 1) << 6);
            asm volatile("cp.async.wait_group 1;");
        } else {
            asm volatile("cp.async.wait_group 0;");
        }
        __syncthreads();
        const uint32_t kvo = (uint32_t)(t & 1) * 8192u;

        // ---- S = Q @ K^T (64x64) ----
        float d[4][4];
        #pragma unroll
        for (int ni = 0; ni < 4; ni++)
            #pragma unroll
            for (int j = 0; j < 4; j++) d[ni][j] = 0.f;

        #pragma unroll
        for (int ks = 0; ks < 4; ks++) {
            const int kb = ks * 16;
            uint32_t a[4], bb[4][2];
            {
                int r  = wm * 16 + (lane & 15);
                int ck = kb + ((lane >> 4) << 3);
                uint32_t addr = baseQ + (uint32_t)r * 128u + (uint32_t)((((ck >> 3) ^ (r & 7))) << 4);
                asm volatile("ldmatrix.sync.aligned.m8n8.x4.shared.b16 {%0,%1,%2,%3}, [%4];"
                             : "=r"(a[0]), "=r"(a[1]), "=r"(a[2]), "=r"(a[3]) : "r"(addr));
            }
            #pragma unroll
            for (int ni = 0; ni < 4; ni++) {
                int r  = wn * 32 + ni * 8 + (lane & 7);
                int ck = kb + (((lane >> 3) & 1) << 3);
                uint32_t addr = baseK + kvo + (uint32_t)r * 128u + (uint32_t)((((ck >> 3) ^ (r & 7))) << 4);
                asm volatile("ldmatrix.sync.aligned.m8n8.x2.shared.b16 {%0,%1}, [%2];"
                             : "=r"(bb[ni][0]), "=r"(bb[ni][1]) : "r"(addr));
            }
            #pragma unroll
            for (int ni = 0; ni < 4; ni++) {
                asm volatile(
                    "mma.sync.aligned.m16n8k16.row.col.f32.f16.f16.f32 "
                    "{%0,%1,%2,%3}, {%4,%5,%6,%7}, {%8,%9}, {%0,%1,%2,%3};"
                    : "+f"(d[ni][0]), "+f"(d[ni][1]), "+f"(d[ni][2]), "+f"(d[ni][3])
                    : "r"(a[0]), "r"(a[1]), "r"(a[2]), "r"(a[3]),
                      "r"(bb[ni][0]), "r"(bb[ni][1]));
            }
        }

        // store S to smem
        {
            const int g = lane >> 2, tq = lane & 3;
            #pragma unroll
            for (int ni = 0; ni < 4; ni++) {
                int rr = wm * 16 + g;
                int cc = wn * 32 + ni * 8 + tq * 2;
                *reinterpret_cast<float2*>(&sS[rr * 64 + cc])       = make_float2(d[ni][0], d[ni][1]);
                *reinterpret_cast<float2*>(&sS[(rr + 8) * 64 + cc]) = make_float2(d[ni][2], d[ni][3]);
            }
        }
        __syncthreads();

        // ---- online softmax: warp w handles rows w*8..w*8+7 ----
        const int k0 = t << 6;
        #pragma unroll
        for (int i = 0; i < 8; i++) {
            int r = warp * 8 + i;
            float v0 = sS[r * 64 + lane] * 0.125f;
            float v1 = sS[r * 64 + lane + 32] * 0.125f;
            if (masked) {
                if (k0 + lane >= limit)      v0 = -3.0e38f;
                if (k0 + lane + 32 >= limit) v1 = -3.0e38f;
            }
            float tm = fmaxf(v0, v1);
            #pragma unroll
            for (int os = 16; os > 0; os >>= 1) tm = fmaxf(tm, __shfl_xor_sync(0xffffffffu, tm, os));
            float mo = sM[r];
            float mn = fmaxf(mo, tm);
            float e0 = __expf(v0 - mn);
            float e1 = __expf(v1 - mn);
            float su = e0 + e1;
            #pragma unroll
            for (int os = 16; os > 0; os >>= 1) su += __shfl_xor_sync(0xffffffffu, su, os);
            if (lane == 0) {
                float fr = __expf(mo - mn);
                sF[r] = fr;
                sL[r] = sL[r] * fr + su;
                sM[r] = mn;
            }
            // write p16 (swizzled) for cols lane, lane+32
            {
                int c = lane;
                uint32_t off = (uint32_t)r * 128u + (uint32_t)((((c >> 3) ^ (r & 7))) << 4) + (uint32_t)((c & 7) << 1);
                *reinterpret_cast<__half*>(smem + 57344 + off) = __float2half(e0);
                c = lane + 32;
                off = (uint32_t)r * 128u + (uint32_t)((((c >> 3) ^ (r & 7))) << 4) + (uint32_t)((c & 7) << 1);
                *reinterpret_cast<__half*>(smem + 57344 + off) = __float2half(e1);
            }
        }
        __syncthreads();

        // ---- rescale O, then O += P @ V ----
        {
            const int g = lane >> 2;
            float f0 = sF[wm * 16 + g];
            float f1 = sF[wm * 16 + 8 + g];
            #pragma unroll
            for (int ni = 0; ni < 4; ni++) {
                o[ni][0] *= f0; o[ni][1] *= f0;
                o[ni][2] *= f1; o[ni][3] *= f1;
            }
        }
        #pragma unroll
        for (int ks = 0; ks < 4; ks++) {
            const int kb = ks * 16;
            uint32_t a[4], bb[4][2];
            {
                int r  = wm * 16 + (lane & 15);
                int ck = kb + ((lane >> 4) << 3);
                uint32_t addr = baseP + (uint32_t)r * 128u + (uint32_t)((((ck >> 3) ^ (r & 7))) << 4);
                asm volatile("ldmatrix.sync.aligned.m8n8.x4.shared.b16 {%0,%1,%2,%3}, [%4];"
                             : "=r"(a[0]), "=r"(a[1]), "=r"(a[2]), "=r"(a[3]) : "r"(addr));
            }
            #pragma unroll
            for (int ni = 0; ni < 4; ni++) {
                int r  = kb + (lane & 15);
                int ck = (wn * 32 + ni * 8) >> 3;
                uint32_t addr = baseV + kvo + (uint32_t)r * 128u + (uint32_t)(((ck ^ (r & 7))) << 4);
                asm volatile("ldmatrix.sync.aligned.m8n8.x2.trans.shared.b16 {%0,%1}, [%2];"
                             : "=r"(bb[ni][0]), "=r"(bb[ni][1]) : "r"(addr));
            }
            #pragma unroll
            for (int ni = 0; ni < 4; ni++) {
                asm volatile(
                    "mma.sync.aligned.m16n8k16.row.col.f32.f16.f16.f32 "
                    "{%0,%1,%2,%3}, {%4,%5,%6,%7}, {%8,%9}, {%0,%1,%2,%3};"
                    : "+f"(o[ni][0]), "+f"(o[ni][1]), "+f"(o[ni][2]), "+f"(o[ni][3])
                    : "r"(a[0]), "r"(a[1]), "r"(a[2]), "r"(a[3]),
                      "r"(bb[ni][0]), "r"(bb[ni][1]));
            }
        }
        __syncthreads();
    }

    // ---- epilogue: O /= l, write fp16; write stats ----
    {
        const int g = lane >> 2, tq = lane & 3;
        float il0 = 1.0f / sL[wm * 16 + g];
        float il1 = 1.0f / sL[wm * 16 + 8 + g];
        __half* Ob = O + ((size_t)b * PLQ + q0) * PE + h * PHD;
        #pragma unroll
        for (int ni = 0; ni < 4; ni++) {
            int rr = wm * 16 + g;
            int cc = wn * 32 + ni * 8 + tq * 2;
            *reinterpret_cast<__half2*>(Ob + (size_t)rr * PE + cc) =
                __floats2half2_rn(o[ni][0] * il0, o[ni][1] * il0);
            *reinterpret_cast<__half2*>(Ob + (size_t)(rr + 8) * PE + cc) =
                __floats2half2_rn(o[ni][2] * il1, o[ni][3] * il1);
        }
    }
    if (stats_m && tid < 64) {
        size_t idx = ((size_t)b * PH + h) * PLQ + q0 + tid;
        stats_m[idx] = sM[tid];
        stats_l[idx] = sL[tid];
    }
}

// ---------------------------------------------------------------------------
// Weights output: per CTA one (b, 64-row q-tile, half of k range).
// Recomputes scores per head from fp16 Q/K, normalizes with stored (m,l),
// accumulates head-mean in regs, writes out_w (zero for invalid q rows).
// Dynamic smem: sQ 0..65536 (64x512 f16, 1024B rows) | sK 65536..81920 (2 stg)
//   sMM 81920 (8x64 f32) | sIL 83968 | total 86016
// ---------------------------------------------------------------------------
__global__ __launch_bounds__(256)
void weights_flash_kernel(const __half* __restrict__ Qp, const __half* __restrict__ Kp,
                          const float* __restrict__ stats_m, const float* __restrict__ stats_l,
                          const int* __restrict__ q_len, float* __restrict__ wout)
{
    extern __shared__ char smem[];
    float* sMM = reinterpret_cast<float*>(smem + 81920);
    float* sIL = reinterpret_cast<float*>(smem + 83968);

    const int q0 = blockIdx.x * 64;
    const int b  = blockIdx.y;
    const int kz = blockIdx.z;          // 0 or 1, each covers 1024 keys
    const int tid = threadIdx.x, lane = tid & 31, warp = tid >> 5;
    const int wm = warp & 3, wn = warp >> 2;
    const int ql = q_len[b];

    const uint32_t baseQ = (uint32_t)__cvta_generic_to_shared(smem);
    const uint32_t baseK = baseQ + 65536u;

    // stats -> smem (8 heads x 64 rows)
    #pragma unroll
    for (int i = 0; i < 2; i++) {
        int j = tid + i * 256;
        int h = j >> 6, r = j & 63;
        size_t idx = ((size_t)b * PH + h) * PLQ + q0 + r;
        sMM[j] = stats_m[idx];
        sIL[j] = 1.0f / stats_l[idx];
    }

    // Q tile all heads: 64 rows x 64 chunks(16B) = 4096, 16/thread
    const __half* Qb = Qp + ((size_t)b * PLQ + q0) * PE;
    #pragma unroll
    for (int i = 0; i < 16; i++) {
        int f = tid + i * 256;
        int r = f >> 6, c = f & 63;
        uint32_t off = (uint32_t)r * 1024u + (uint32_t)((((c & 7) ^ (r & 7)) | (c & 56)) << 4);
        cpasync16(baseQ + off, Qb + (size_t)r * PE + c * 8);
    }
    cpcommit();

    const __half* Kbase = Kp + ((size_t)b * PLK + kz * 1024) * PE;
    auto loadK = [&](int stage, int it) {
        int kt = it >> 3, h = it & 7;
        #pragma unroll
        for (int i = 0; i < 2; i++) {
            int f = tid + i * 256;
            int r = f >> 3, c = f & 7;
            cpasync16(baseK + stage * 8192u + (uint32_t)r * 128u + (uint32_t)((c ^ (r & 7)) << 4),
                      Kbase + (size_t)(kt * 64 + r) * PE + h * PHD + c * 8);
        }
        cpcommit();
    };
    loadK(0, 0);

    float acc[4][4];
    const int g = lane >> 2, tq = lane & 3;
    const int rr  = wm * 16 + g;
    const int rr8 = rr + 8;
    const bool v0 = (q0 + rr)  < ql;
    const bool v1 = (q0 + rr8) < ql;

    for (int it = 0; it < 128; it++) {
        const int kt = it >> 3, h = it & 7;
        if (h == 0) {
            #pragma unroll
            for (int ni = 0; ni < 4; ni++)
                #pragma unroll
                for (int j = 0; j < 4; j++) acc[ni][j] = 0.f;
        }
        if (it + 1 < 128) {
            loadK((it + 1) & 1, it + 1);
            asm volatile("cp.async.wait_group 1;");
        } else {
            asm volatile("cp.async.wait_group 0;");
        }
        __syncthreads();
        const uint32_t ko = (uint32_t)(it & 1) * 8192u;

        float d[4][4];
        #pragma unroll
        for (int ni = 0; ni < 4; ni++)
            #pragma unroll
            for (int j = 0; j < 4; j++) d[ni][j] = 0.f;

        #pragma unroll
        for (int ks = 0; ks < 4; ks++) {
            const int kb = ks * 16;
            uint32_t a[4], bb[4][2];
            {
                int r = wm * 16 + (lane & 15);
                int c = h * 8 + (kb >> 3) + (lane >> 4);
                uint32_t addr = baseQ + (uint32_t)r * 1024u + (uint32_t)((((c & 7) ^ (r & 7)) | (c & 56)) << 4);
                asm volatile("ldmatrix.sync.aligned.m8n8.x4.shared.b16 {%0,%1,%2,%3}, [%4];"
                             : "=r"(a[0]), "=r"(a[1]), "=r"(a[2]), "=r"(a[3]) : "r"(addr));
            }
            #pragma unroll
            for (int ni = 0; ni < 4; ni++) {
                int r  = wn * 32 + ni * 8 + (lane & 7);
                int ck = kb + (((lane >> 3) & 1) << 3);
                uint32_t addr = baseK + ko + (uint32_t)r * 128u + (uint32_t)((((ck >> 3) ^ (r & 7))) << 4);
                asm volatile("ldmatrix.sync.aligned.m8n8.x2.shared.b16 {%0,%1}, [%2];"
                             : "=r"(bb[ni][0]), "=r"(bb[ni][1]) : "r"(addr));
            }
            #pragma unroll
            for (int ni = 0; ni < 4; ni++) {
                asm volatile(
                    "mma.sync.aligned.m16n8k16.row.col.f32.f16.f16.f32 "
                    "{%0,%1,%2,%3}, {%4,%5,%6,%7}, {%8,%9}, {%0,%1,%2,%3};"
                    : "+f"(d[ni][0]), "+f"(d[ni][1]), "+f"(d[ni][2]), "+f"(d[ni][3])
                    : "r"(a[0]), "r"(a[1]), "r"(a[2]), "r"(a[3]),
                      "r"(bb[ni][0]), "r"(bb[ni][1]));
            }
        }

        // p = exp(s*scale - m) / l, accumulate over heads
        {
            float m0 = sMM[h * 64 + rr],  i0 = sIL[h * 64 + rr];
            float m1 = sMM[h * 64 + rr8], i1 = sIL[h * 64 + rr8];
            #pragma unroll
            for (int ni = 0; ni < 4; ni++) {
                acc[ni][0] += __expf(d[ni][0] * 0.125f - m0) * i0;
                acc[ni][1] += __expf(d[ni][1] * 0.125f - m0) * i0;
                acc[ni][2] += __expf(d[ni][2] * 0.125f - m1) * i1;
                acc[ni][3] += __expf(d[ni][3] * 0.125f - m1) * i1;
            }
        }

        if (h == 7) {
            int kbase = kz * 1024 + kt * 64;
            #pragma unroll
            for (int ni = 0; ni < 4; ni++) {
                int cc = kbase + wn * 32 + ni * 8 + tq * 2;
                float2 w0 = v0 ? make_float2(acc[ni][0] * 0.125f, acc[ni][1] * 0.125f)
                               : make_float2(0.f, 0.f);
                float2 w1 = v1 ? make_float2(acc[ni][2] * 0.125f, acc[ni][3] * 0.125f)
                               : make_float2(0.f, 0.f);
                *reinterpret_cast<float2*>(wout + ((size_t)b * PLQ + q0 + rr)  * PLK + cc) = w0;
                *reinterpret_cast<float2*>(wout + ((size_t)b * PLQ + q0 + rr8) * PLK + cc) = w1;
            }
        }
        __syncthreads();
    }
}

// ---------------------------------------------------------------------------
// fp32 -> fp16 convert (n % 4 == 0)
// ---------------------------------------------------------------------------
__global__ void f32_to_f16_kernel(const float* __restrict__ in, __half* __restrict__ out, int n)
{
    int i = (blockIdx.x * blockDim.x + threadIdx.x) * 4;
    if (i >= n) return;
    float4 v = *reinterpret_cast<const float4*>(in + i);
    __half2* o = reinterpret_cast<__half2*>(out + i);
    o[0] = __floats2half2_rn(v.x, v.y);
    o[1] = __floats2half2_rn(v.z, v.w);
}

// ---------------------------------------------------------------------------
// Mask invalid query rows: out32/out16[r,:] = valid ? in : 0
// ---------------------------------------------------------------------------
__global__ void mask_rows_kernel(const float* __restrict__ in, float* __restrict__ out32,
                                 __half* __restrict__ out16, const int* __restrict__ q_len)
{
    int r = blockIdx.x;
    bool valid = (r % PLQ) < q_len[r / PLQ];
    const float4* src = reinterpret_cast<const float4*>(in + (size_t)r * PE);
    float4* dst = reinterpret_cast<float4*>(out32 + (size_t)r * PE);
    __half2* dh = reinterpret_cast<__half2*>(out16 + (size_t)r * PE);
    for (int c = threadIdx.x; c < PE / 4; c += blockDim.x) {
        float4 v = valid ? src[c] : make_float4(0.f, 0.f, 0.f, 0.f);
        dst[c] = v;
        dh[c * 2]     = __floats2half2_rn(v.x, v.y);
        dh[c * 2 + 1] = __floats2half2_rn(v.z, v.w);
    }
}

// ---------------------------------------------------------------------------
// out[r,:] = LN( silu(X + Y) )*g + b ; optional fp16 copy; optional zero rows
// ---------------------------------------------------------------------------
__global__ __launch_bounds__(128)
void add_silu_ln_kernel(const float* __restrict__ X, const float* __restrict__ Y,
                        const float* __restrict__ g, const float* __restrict__ bln,
                        float* __restrict__ out, __half* __restrict__ out16,
                        const int* __restrict__ q_len, int zero_invalid)
{
    constexpr int D = 512;
    int r = blockIdx.x;
    int tid = threadIdx.x;
    int c = tid * 4;

    float4 x = *reinterpret_cast<const float4*>(X + (size_t)r * D + c);
    float4 y = *reinterpret_cast<const float4*>(Y + (size_t)r * D + c);
    float v[4] = {x.x + y.x, x.y + y.y, x.z + y.z, x.w + y.w};

    float s[4], sum = 0.f, sumsq = 0.f;
    #pragma unroll
    for (int i = 0; i < 4; i++) {
        s[i] = v[i] / (1.0f + __expf(-v[i]));
        sum += s[i];
        sumsq += s[i] * s[i];
    }

    __shared__ float r1[128], r2[128];
    r1[tid] = sum; r2[tid] = sumsq; __syncthreads();
    for (int st = 64; st > 0; st >>= 1) {
        if (tid < st) { r1[tid] += r1[tid + st]; r2[tid] += r2[tid + st]; }
        __syncthreads();
    }
    float mu  = r1[0] * (1.0f / D);
    float var = r2[0] * (1.0f / D) - mu * mu;
    float rs  = rsqrtf(var + 1e-5f);

    bool zero = zero_invalid && ((r % PLQ) >= q_len[r / PLQ]);

    float4 gg = *reinterpret_cast<const float4*>(g + c);
    float4 bb = *reinterpret_cast<const float4*>(bln + c);
    float4 o;
    o.x = zero ? 0.f : (s[0] - mu) * rs * gg.x + bb.x;
    o.y = zero ? 0.f : (s[1] - mu) * rs * gg.y + bb.y;
    o.z = zero ? 0.f : (s[2] - mu) * rs * gg.z + bb.z;
    o.w = zero ? 0.f : (s[3] - mu) * rs * gg.w + bb.w;
    *reinterpret_cast<float4*>(out + (size_t)r * D + c) = o;
    if (out16) {
        __half2* oh = reinterpret_cast<__half2*>(out16 + (size_t)r * D + c);
        oh[0] = __floats2half2_rn(o.x, o.y);
        oh[1] = __floats2half2_rn(o.z, o.w);
    }
}

// ---------------------------------------------------------------------------
// Host launcher
// ---------------------------------------------------------------------------
static void launch_gemm(const __half* A, int lda,
                        const __half* Bm, int ldb,
                        float* C32, __half* C16, int ldc,
                        const float* bias, int M, int N, int K)
{
    dim3 grid(N / 64, M / 128, 1);
    hgemm2_kernel<1><<<grid, 256>>>(A, lda, 0, 0, Bm, ldb, 0, 0,
                                    C32, C16, ldc, 0, 0, bias, M, N, K, 1.f, 1);
}

extern "C" void kernel_launch(void* const* d_in, const int* in_sizes, int n_in,
                              void* d_out, int out_size)
{
    const float* queries = (const float*)d_in[0];
    const float* keys    = (const float*)d_in[1];
    const int*   q_len   = (const int*)  d_in[2];
    const float* cWq = (const float*)d_in[3];  const float* cbq = (const float*)d_in[4];
    const float* cWk = (const float*)d_in[5];  const float* cbk = (const float*)d_in[6];
    const float* cWv = (const float*)d_in[7];  const float* cbv = (const float*)d_in[8];
    const float* cWo = (const float*)d_in[9];  const float* cbo = (const float*)d_in[10];
    const float* sWq = (const float*)d_in[11]; const float* sbq = (const float*)d_in[12];
    const float* sWk = (const float*)d_in[13]; const float* sbk = (const float*)d_in[14];
    const float* sWv = (const float*)d_in[15]; const float* sbv = (const float*)d_in[16];
    const float* sWo = (const float*)d_in[17]; const float* sbo = (const float*)d_in[18];
    const float* Wf  = (const float*)d_in[19]; const float* bf  = (const float*)d_in[20];
    const float* g_cross = (const float*)d_in[21]; const float* b_cross = (const float*)d_in[22];
    const float* g_ffn   = (const float*)d_in[23]; const float* b_ffn   = (const float*)d_in[24];
    const float* g_self  = (const float*)d_in[25]; const float* b_self  = (const float*)d_in[26];

    float* out_q = (float*)d_out;
    float* out_w = out_q + (size_t)PB * PLQ * PHID;

    float *QM, *Pp, *X1, *Fb, *X2, *sm, *sl;
    __half *w16, *keys16, *QM16, *Qp16, *Kp16, *Vp16, *Op16, *X116, *X216;
    cudaGetSymbolAddress((void**)&QM,   g_QM);
    cudaGetSymbolAddress((void**)&Pp,   g_Pp);
    cudaGetSymbolAddress((void**)&X1,   g_X1);
    cudaGetSymbolAddress((void**)&Fb,   g_Fb);
    cudaGetSymbolAddress((void**)&X2,   g_X2);
    cudaGetSymbolAddress((void**)&sm,   g_sm);
    cudaGetSymbolAddress((void**)&sl,   g_sl);
    cudaGetSymbolAddress((void**)&w16,  g_w16);
    cudaGetSymbolAddress((void**)&keys16, g_keys16);
    cudaGetSymbolAddress((void**)&QM16, g_QM16);
    cudaGetSymbolAddress((void**)&Qp16, g_Qp16);
    cudaGetSymbolAddress((void**)&Kp16, g_Kp16);
    cudaGetSymbolAddress((void**)&Vp16, g_Vp16);
    cudaGetSymbolAddress((void**)&Op16, g_Op16);
    cudaGetSymbolAddress((void**)&X116, g_X116);
    cudaGetSymbolAddress((void**)&X216, g_X216);

    cudaFuncSetAttribute(flash_kernel, cudaFuncAttributeMaxDynamicSharedMemorySize, 66304);
    cudaFuncSetAttribute(weights_flash_kernel, cudaFuncAttributeMaxDynamicSharedMemorySize, 86016);

    const int MQ = PB * PLQ;   // 4096
    const int MK = PB * PLK;   // 8192

    // 0) convert weights + keys to fp16
    const float* Ws[9] = {cWq, cWk, cWv, cWo, sWq, sWk, sWv, sWo, Wf};
    for (int i = 0; i < 9; i++)
        f32_to_f16_kernel<<<(PE * PE) / 1024, 256>>>(Ws[i], w16 + (size_t)i * PE * PE, PE * PE);
    f32_to_f16_kernel<<<(MK * PE) / 1024, 256>>>(keys, keys16, MK * PE);

    // 1) masked queries (fp32 + fp16)
    mask_rows_kernel<<<MQ, 128>>>(queries, QM, QM16, q_len);

    // 2) cross projections (fp16 out)
    launch_gemm(QM16,   PE, w16 + 0*PE*PE, PE, nullptr, Qp16, PE, cbq, MQ, PE, PE);
    launch_gemm(keys16, PE, w16 + 1*PE*PE, PE, nullptr, Kp16, PE, cbk, MK, PE, PE);
    launch_gemm(keys16, PE, w16 + 2*PE*PE, PE, nullptr, Vp16, PE, cbv, MK, PE, PE);

    // 3) fused cross attention -> Op16 (+ stats for weights)
    flash_kernel<<<dim3(PLQ / 64, PH, PB), 256, 66304>>>(
        Qp16, Kp16, Vp16, Op16, sm, sl, PLK, 0, q_len);

    // 4) attention weights output (head mean, invalid q rows zeroed)
    weights_flash_kernel<<<dim3(PLQ / 64, PB, 2), 256, 86016>>>(
        Qp16, Kp16, sm, sl, q_len, out_w);

    // 5) cross out-projection (fp32)
    launch_gemm(Op16, PE, w16 + 3*PE*PE, PE, Pp, nullptr, PE, cbo, MQ, PE, PE);

    // 6) x1 = LN(silu(cross + qm))
    add_silu_ln_kernel<<<MQ, 128>>>(Pp, QM, g_cross, b_cross, X1, X116, q_len, 0);

    // 7) FFN + LN
    launch_gemm(X116, PE, w16 + 8*PE*PE, PE, Fb, nullptr, PHID, bf, MQ, PHID, PE);
    add_silu_ln_kernel<<<MQ, 128>>>(X1, Fb, g_ffn, b_ffn, X2, X216, q_len, 0);

    // 8) self projections (fp16)
    launch_gemm(X216, PHID, w16 + 4*PE*PE, PHID, nullptr, Qp16, PHID, sbq, MQ, PHID, PHID);
    launch_gemm(X216, PHID, w16 + 5*PE*PE, PHID, nullptr, Kp16, PHID, sbk, MQ, PHID, PHID);
    launch_gemm(X216, PHID, w16 + 6*PE*PE, PHID, nullptr, Vp16, PHID, sbv, MQ, PHID, PHID);

    // 9) fused self attention (masked keys) -> Op16
    flash_kernel<<<dim3(PLQ / 64, PH, PB), 256, 66304>>>(
        Qp16, Kp16, Vp16, Op16, nullptr, nullptr, PLQ, 1, q_len);

    // 10) self out-projection (fp32)
    launch_gemm(Op16, PHID, w16 + 7*PE*PE, PHID, Pp, nullptr, PHID, sbo, MQ, PHID, PHID);

    // 11) final: out = LN(silu(x2 + so)), invalid rows zeroed
    add_silu_ln_kernel<<<MQ, 128>>>(X2, Pp, g_self, b_self, out_q, nullptr, q_len, 1);
}

// round 5
// speedup vs baseline: 3.2828x; 1.0551x over previous
#include <cuda_runtime.h>
#include <cuda_fp16.h>
#include <cstdint>
#include <cstddef>

// Problem constants
#define PB   4
#define PLQ  1024
#define PLK  2048
#define PE   512
#define PHID 512
#define PH   8
#define PHD  64

// ---------------------------------------------------------------------------
// Scratch (__device__ globals; no runtime allocation allowed)
// ---------------------------------------------------------------------------
__device__ float  g_QM[PB * PLQ * PE];                 // masked queries fp32 (residual)
__device__ float  g_Pp[PB * PLQ * PE];                 // out-projection fp32
__device__ float  g_X1[PB * PLQ * PE];                 // after cross LN fp32
__device__ float  g_Fb[PB * PLQ * PHID];               // FFN fp32
__device__ float  g_X2[PB * PLQ * PHID];               // after FFN LN fp32

__device__ __half g_w16 [9 * PE * PE];                 // cWq,cWk,cWv,cWo,sWq,sWk,sWv,sWo,Wf
__device__ __half g_keys16[PB * PLK * PE];
__device__ __half g_QM16 [PB * PLQ * PE];
__device__ __half g_Qp16 [PB * PLK * PE];
__device__ __half g_Kp16 [PB * PLK * PE];
__device__ __half g_Vp16 [PB * PLK * PE];
__device__ __half g_Op16 [PB * PLQ * PE];
__device__ __half g_X116 [PB * PLQ * PE];
__device__ __half g_X216 [PB * PLQ * PE];

__device__ float  g_sm[PB * PH * PLQ];                 // cross softmax row max (scaled)
__device__ float  g_sl[PB * PH * PLQ];                 // cross softmax row sum

// ---------------------------------------------------------------------------
// cp.async helpers
// ---------------------------------------------------------------------------
__device__ __forceinline__ void cpasync16(uint32_t dst, const void* src) {
    asm volatile("cp.async.cg.shared.global [%0], [%1], 16;" :: "r"(dst), "l"(src));
}
__device__ __forceinline__ void cpcommit() {
    asm volatile("cp.async.commit_group;");
}

// ---------------------------------------------------------------------------
// 3-stage pipelined tensor-core HGEMM: C = A @ B^T + bias
//   A [M,K] f16 row-major, B [N,K] f16 row-major, C f32 and/or f16.
// CTA tile 128x128x64; 8 warps as 2(M) x 4(N); warp tile 64x32.
// Dynamic smem: sA 3*16KB @0, sB 3*16KB @49152; total 98304.
// Requires M%128==0, N%128==0, K%64==0 (K>=128 for pipeline; all calls K=512).
// ---------------------------------------------------------------------------
__global__ __launch_bounds__(256)
void hgemm3_kernel(const __half* __restrict__ A, int lda,
                   const __half* __restrict__ Bm, int ldb,
                   float* __restrict__ C32, __half* __restrict__ C16,
                   int ldc, const float* __restrict__ bias,
                   int M, int N, int K)
{
    extern __shared__ char smem[];
    const uint32_t baseA = (uint32_t)__cvta_generic_to_shared(smem);
    const uint32_t baseB = baseA + 49152u;

    const int tid  = threadIdx.x;
    const int lane = tid & 31;
    const int warp = tid >> 5;
    const int wm   = warp >> 2;         // 0..1 -> M offset wm*64
    const int wn   = warp & 3;          // 0..3 -> N offset wn*32
    const int m0   = blockIdx.y * 128;
    const int n0   = blockIdx.x * 128;

    auto load_tile = [&](int stage, int k0) {
        #pragma unroll
        for (int i = 0; i < 4; i++) {
            int f = tid + i * 256;
            int r = f >> 3, c = f & 7;
            cpasync16(baseA + (uint32_t)stage * 16384u + (uint32_t)r * 128u + (uint32_t)((c ^ (r & 7)) << 4),
                      A + (size_t)(m0 + r) * lda + k0 + c * 8);
        }
        #pragma unroll
        for (int i = 0; i < 4; i++) {
            int f = tid + i * 256;
            int r = f >> 3, c = f & 7;
            cpasync16(baseB + (uint32_t)stage * 16384u + (uint32_t)r * 128u + (uint32_t)((c ^ (r & 7)) << 4),
                      Bm + (size_t)(n0 + r) * ldb + k0 + c * 8);
        }
        cpcommit();
    };

    float d[4][4][4];
    #pragma unroll
    for (int mi = 0; mi < 4; mi++)
        #pragma unroll
        for (int ni = 0; ni < 4; ni++)
            #pragma unroll
            for (int j = 0; j < 4; j++) d[mi][ni][j] = 0.f;

    const int nt = K >> 6;
    load_tile(0, 0);
    if (nt > 1) load_tile(1, 64);

    for (int t = 0; t < nt; t++) {
        if (t < nt - 1) { asm volatile("cp.async.wait_group 1;"); }
        else            { asm volatile("cp.async.wait_group 0;"); }
        __syncthreads();
        if (t + 2 < nt) load_tile((t + 2) % 3, (t + 2) << 6);

        const uint32_t stA = baseA + (uint32_t)(t % 3) * 16384u;
        const uint32_t stB = baseB + (uint32_t)(t % 3) * 16384u;

        #pragma unroll
        for (int ks = 0; ks < 4; ks++) {
            const int kb = ks * 16;
            uint32_t a[4][4], b[4][2];
            #pragma unroll
            for (int mi = 0; mi < 4; mi++) {
                int r  = wm * 64 + mi * 16 + (lane & 15);
                int ck = kb + ((lane >> 4) << 3);
                uint32_t addr = stA + (uint32_t)r * 128u + (uint32_t)((((ck >> 3) ^ (r & 7))) << 4);
                asm volatile("ldmatrix.sync.aligned.m8n8.x4.shared.b16 {%0,%1,%2,%3}, [%4];"
                             : "=r"(a[mi][0]), "=r"(a[mi][1]), "=r"(a[mi][2]), "=r"(a[mi][3])
                             : "r"(addr));
            }
            #pragma unroll
            for (int ni = 0; ni < 4; ni++) {
                int r  = wn * 32 + ni * 8 + (lane & 7);
                int ck = kb + (((lane >> 3) & 1) << 3);
                uint32_t addr = stB + (uint32_t)r * 128u + (uint32_t)((((ck >> 3) ^ (r & 7))) << 4);
                asm volatile("ldmatrix.sync.aligned.m8n8.x2.shared.b16 {%0,%1}, [%2];"
                             : "=r"(b[ni][0]), "=r"(b[ni][1])
                             : "r"(addr));
            }
            #pragma unroll
            for (int mi = 0; mi < 4; mi++)
                #pragma unroll
                for (int ni = 0; ni < 4; ni++) {
                    asm volatile(
                        "mma.sync.aligned.m16n8k16.row.col.f32.f16.f16.f32 "
                        "{%0,%1,%2,%3}, {%4,%5,%6,%7}, {%8,%9}, {%0,%1,%2,%3};"
                        : "+f"(d[mi][ni][0]), "+f"(d[mi][ni][1]),
                          "+f"(d[mi][ni][2]), "+f"(d[mi][ni][3])
                        : "r"(a[mi][0]), "r"(a[mi][1]), "r"(a[mi][2]), "r"(a[mi][3]),
                          "r"(b[ni][0]), "r"(b[ni][1]));
                }
        }
        __syncthreads();
    }

    const int g = lane >> 2, tq = lane & 3;
    #pragma unroll
    for (int mi = 0; mi < 4; mi++) {
        #pragma unroll
        for (int ni = 0; ni < 4; ni++) {
            int rr = m0 + wm * 64 + mi * 16 + g;
            int cc = n0 + wn * 32 + ni * 8 + tq * 2;
            float b0 = 0.f, b1 = 0.f;
            if (bias) { b0 = bias[cc]; b1 = bias[cc + 1]; }
            float o00 = d[mi][ni][0] + b0, o01 = d[mi][ni][1] + b1;
            float o10 = d[mi][ni][2] + b0, o11 = d[mi][ni][3] + b1;
            if (C32) {
                *reinterpret_cast<float2*>(C32 + (size_t)rr * ldc + cc)       = make_float2(o00, o01);
                *reinterpret_cast<float2*>(C32 + (size_t)(rr + 8) * ldc + cc) = make_float2(o10, o11);
            }
            if (C16) {
                *reinterpret_cast<__half2*>(C16 + (size_t)rr * ldc + cc)       = __floats2half2_rn(o00, o01);
                *reinterpret_cast<__half2*>(C16 + (size_t)(rr + 8) * ldc + cc) = __floats2half2_rn(o10, o11);
            }
        }
    }
}

// ---------------------------------------------------------------------------
// Fused flash attention: per CTA one (b, h, 64-row q-tile).
// Online softmax with running (m, l); O accumulated in regs with rescale.
// Writes O (fp16, head-sliced [*,E] layout) and optional per-row stats (m,l).
// masked=1: only keys k < q_len[b] participate.
// Dynamic smem layout (bytes):
//   sQ 0..8192 | sK 8192..24576 (2 stg) | sV 24576..40960 (2 stg)
//   sS 40960..57344 (f32 64x64) | sP 57344..65536 (f16 64x64)
//   sM 65536 | sL 65792 | sF 66048 | total 66304
// ---------------------------------------------------------------------------
__global__ __launch_bounds__(256)
void flash_kernel(const __half* __restrict__ Q, const __half* __restrict__ K,
                  const __half* __restrict__ V, __half* __restrict__ O,
                  float* __restrict__ stats_m, float* __restrict__ stats_l,
                  int LK, int masked, const int* __restrict__ q_len)
{
    extern __shared__ char smem[];
    float*  sS = reinterpret_cast<float*>(smem + 40960);
    float*  sM = reinterpret_cast<float*>(smem + 65536);
    float*  sL = reinterpret_cast<float*>(smem + 65792);
    float*  sF = reinterpret_cast<float*>(smem + 66048);

    const int b = blockIdx.z, h = blockIdx.y, q0 = blockIdx.x * 64;
    const int tid = threadIdx.x, lane = tid & 31, warp = tid >> 5;
    const int wm = warp & 3, wn = warp >> 2;

    const int limit = masked ? q_len[b] : LK;
    const int nt = (limit + 63) >> 6;

    const __half* Qb = Q + ((size_t)b * PLQ + q0) * PE + h * PHD;
    const __half* Kb = K + ((size_t)b * LK) * PE + h * PHD;
    const __half* Vb = V + ((size_t)b * LK) * PE + h * PHD;

    const uint32_t baseQ = (uint32_t)__cvta_generic_to_shared(smem);
    const uint32_t baseK = baseQ + 8192;
    const uint32_t baseV = baseQ + 24576;
    const uint32_t baseP = baseQ + 57344;

    if (tid < 64) { sM[tid] = -3.0e38f; sL[tid] = 0.f; }

    #pragma unroll
    for (int i = 0; i < 2; i++) {
        int f = tid + i * 256;
        int r = f >> 3, c = f & 7;
        cpasync16(baseQ + (uint32_t)r * 128u + (uint32_t)((c ^ (r & 7)) << 4),
                  Qb + (size_t)r * PE + c * 8);
    }
    cpcommit();

    auto loadKV = [&](int stage, int k0) {
        #pragma unroll
        for (int i = 0; i < 2; i++) {
            int f = tid + i * 256;
            int r = f >> 3, c = f & 7;
            cpasync16(baseK + stage * 8192u + (uint32_t)r * 128u + (uint32_t)((c ^ (r & 7)) << 4),
                      Kb + (size_t)(k0 + r) * PE + c * 8);
        }
        #pragma unroll
        for (int i = 0; i < 2; i++) {
            int f = tid + i * 256;
            int r = f >> 3, c = f & 7;
            cpasync16(baseV + stage * 8192u + (uint32_t)r * 128u + (uint32_t)((c ^ (r & 7)) << 4),
                      Vb + (size_t)(k0 + r) * PE + c * 8);
        }
        cpcommit();
    };
    loadKV(0, 0);

    float o[4][4];
    #pragma unroll
    for (int ni = 0; ni < 4; ni++)
        #pragma unroll
        for (int j = 0; j < 4; j++) o[ni][j] = 0.f;

    for (int t = 0; t < nt; t++) {
        if (t + 1 < nt) {
            loadKV((t + 1) & 1, (t + 1) << 6);
            asm volatile("cp.async.wait_group 1;");
        } else {
            asm volatile("cp.async.wait_group 0;");
        }
        __syncthreads();
        const uint32_t kvo = (uint32_t)(t & 1) * 8192u;

        // ---- S = Q @ K^T (64x64) ----
        float d[4][4];
        #pragma unroll
        for (int ni = 0; ni < 4; ni++)
            #pragma unroll
            for (int j = 0; j < 4; j++) d[ni][j] = 0.f;

        #pragma unroll
        for (int ks = 0; ks < 4; ks++) {
            const int kb = ks * 16;
            uint32_t a[4], bb[4][2];
            {
                int r  = wm * 16 + (lane & 15);
                int ck = kb + ((lane >> 4) << 3);
                uint32_t addr = baseQ + (uint32_t)r * 128u + (uint32_t)((((ck >> 3) ^ (r & 7))) << 4);
                asm volatile("ldmatrix.sync.aligned.m8n8.x4.shared.b16 {%0,%1,%2,%3}, [%4];"
                             : "=r"(a[0]), "=r"(a[1]), "=r"(a[2]), "=r"(a[3]) : "r"(addr));
            }
            #pragma unroll
            for (int ni = 0; ni < 4; ni++) {
                int r  = wn * 32 + ni * 8 + (lane & 7);
                int ck = kb + (((lane >> 3) & 1) << 3);
                uint32_t addr = baseK + kvo + (uint32_t)r * 128u + (uint32_t)((((ck >> 3) ^ (r & 7))) << 4);
                asm volatile("ldmatrix.sync.aligned.m8n8.x2.shared.b16 {%0,%1}, [%2];"
                             : "=r"(bb[ni][0]), "=r"(bb[ni][1]) : "r"(addr));
            }
            #pragma unroll
            for (int ni = 0; ni < 4; ni++) {
                asm volatile(
                    "mma.sync.aligned.m16n8k16.row.col.f32.f16.f16.f32 "
                    "{%0,%1,%2,%3}, {%4,%5,%6,%7}, {%8,%9}, {%0,%1,%2,%3};"
                    : "+f"(d[ni][0]), "+f"(d[ni][1]), "+f"(d[ni][2]), "+f"(d[ni][3])
                    : "r"(a[0]), "r"(a[1]), "r"(a[2]), "r"(a[3]),
                      "r"(bb[ni][0]), "r"(bb[ni][1]));
            }
        }

        {
            const int g = lane >> 2, tq = lane & 3;
            #pragma unroll
            for (int ni = 0; ni < 4; ni++) {
                int rr = wm * 16 + g;
                int cc = wn * 32 + ni * 8 + tq * 2;
                *reinterpret_cast<float2*>(&sS[rr * 64 + cc])       = make_float2(d[ni][0], d[ni][1]);
                *reinterpret_cast<float2*>(&sS[(rr + 8) * 64 + cc]) = make_float2(d[ni][2], d[ni][3]);
            }
        }
        __syncthreads();

        // ---- online softmax: warp w handles rows w*8..w*8+7 ----
        const int k0 = t << 6;
        #pragma unroll
        for (int i = 0; i < 8; i++) {
            int r = warp * 8 + i;
            float v0 = sS[r * 64 + lane] * 0.125f;
            float v1 = sS[r * 64 + lane + 32] * 0.125f;
            if (masked) {
                if (k0 + lane >= limit)      v0 = -3.0e38f;
                if (k0 + lane + 32 >= limit) v1 = -3.0e38f;
            }
            float tm = fmaxf(v0, v1);
            #pragma unroll
            for (int os = 16; os > 0; os >>= 1) tm = fmaxf(tm, __shfl_xor_sync(0xffffffffu, tm, os));
            float mo = sM[r];
            float mn = fmaxf(mo, tm);
            float e0 = __expf(v0 - mn);
            float e1 = __expf(v1 - mn);
            float su = e0 + e1;
            #pragma unroll
            for (int os = 16; os > 0; os >>= 1) su += __shfl_xor_sync(0xffffffffu, su, os);
            if (lane == 0) {
                float fr = __expf(mo - mn);
                sF[r] = fr;
                sL[r] = sL[r] * fr + su;
                sM[r] = mn;
            }
            {
                int c = lane;
                uint32_t off = (uint32_t)r * 128u + (uint32_t)((((c >> 3) ^ (r & 7))) << 4) + (uint32_t)((c & 7) << 1);
                *reinterpret_cast<__half*>(smem + 57344 + off) = __float2half(e0);
                c = lane + 32;
                off = (uint32_t)r * 128u + (uint32_t)((((c >> 3) ^ (r & 7))) << 4) + (uint32_t)((c & 7) << 1);
                *reinterpret_cast<__half*>(smem + 57344 + off) = __float2half(e1);
            }
        }
        __syncthreads();

        // ---- rescale O, then O += P @ V ----
        {
            const int g = lane >> 2;
            float f0 = sF[wm * 16 + g];
            float f1 = sF[wm * 16 + 8 + g];
            #pragma unroll
            for (int ni = 0; ni < 4; ni++) {
                o[ni][0] *= f0; o[ni][1] *= f0;
                o[ni][2] *= f1; o[ni][3] *= f1;
            }
        }
        #pragma unroll
        for (int ks = 0; ks < 4; ks++) {
            const int kb = ks * 16;
            uint32_t a[4], bb[4][2];
            {
                int r  = wm * 16 + (lane & 15);
                int ck = kb + ((lane >> 4) << 3);
                uint32_t addr = baseP + (uint32_t)r * 128u + (uint32_t)((((ck >> 3) ^ (r & 7))) << 4);
                asm volatile("ldmatrix.sync.aligned.m8n8.x4.shared.b16 {%0,%1,%2,%3}, [%4];"
                             : "=r"(a[0]), "=r"(a[1]), "=r"(a[2]), "=r"(a[3]) : "r"(addr));
            }
            #pragma unroll
            for (int ni = 0; ni < 4; ni++) {
                int r  = kb + (lane & 15);
                int ck = (wn * 32 + ni * 8) >> 3;
                uint32_t addr = baseV + kvo + (uint32_t)r * 128u + (uint32_t)(((ck ^ (r & 7))) << 4);
                asm volatile("ldmatrix.sync.aligned.m8n8.x2.trans.shared.b16 {%0,%1}, [%2];"
                             : "=r"(bb[ni][0]), "=r"(bb[ni][1]) : "r"(addr));
            }
            #pragma unroll
            for (int ni = 0; ni < 4; ni++) {
                asm volatile(
                    "mma.sync.aligned.m16n8k16.row.col.f32.f16.f16.f32 "
                    "{%0,%1,%2,%3}, {%4,%5,%6,%7}, {%8,%9}, {%0,%1,%2,%3};"
                    : "+f"(o[ni][0]), "+f"(o[ni][1]), "+f"(o[ni][2]), "+f"(o[ni][3])
                    : "r"(a[0]), "r"(a[1]), "r"(a[2]), "r"(a[3]),
                      "r"(bb[ni][0]), "r"(bb[ni][1]));
            }
        }
        __syncthreads();
    }

    {
        const int g = lane >> 2, tq = lane & 3;
        float il0 = 1.0f / sL[wm * 16 + g];
        float il1 = 1.0f / sL[wm * 16 + 8 + g];
        __half* Ob = O + ((size_t)b * PLQ + q0) * PE + h * PHD;
        #pragma unroll
        for (int ni = 0; ni < 4; ni++) {
            int rr = wm * 16 + g;
            int cc = wn * 32 + ni * 8 + tq * 2;
            *reinterpret_cast<__half2*>(Ob + (size_t)rr * PE + cc) =
                __floats2half2_rn(o[ni][0] * il0, o[ni][1] * il0);
            *reinterpret_cast<__half2*>(Ob + (size_t)(rr + 8) * PE + cc) =
                __floats2half2_rn(o[ni][2] * il1, o[ni][3] * il1);
        }
    }
    if (stats_m && tid < 64) {
        size_t idx = ((size_t)b * PH + h) * PLQ + q0 + tid;
        stats_m[idx] = sM[tid];
        stats_l[idx] = sL[tid];
    }
}

// ---------------------------------------------------------------------------
// Weights output: per CTA one (b, 64-row q-tile, 1/8 of k range = 256 keys).
// Recomputes scores per head from fp16 Q/K, normalizes with stored (m,l),
// accumulates head-mean in regs, writes out_w (zero for invalid q rows).
// Dynamic smem: sQ 0..65536 (64x512 f16, 1024B rows) | sK 65536..81920 (2 stg)
//   sMM 81920 (8x64 f32) | sIL 83968 | total 86016
// ---------------------------------------------------------------------------
__global__ __launch_bounds__(256)
void weights_flash_kernel(const __half* __restrict__ Qp, const __half* __restrict__ Kp,
                          const float* __restrict__ stats_m, const float* __restrict__ stats_l,
                          const int* __restrict__ q_len, float* __restrict__ wout)
{
    extern __shared__ char smem[];
    float* sMM = reinterpret_cast<float*>(smem + 81920);
    float* sIL = reinterpret_cast<float*>(smem + 83968);

    const int q0 = blockIdx.x * 64;
    const int b  = blockIdx.y;
    const int kz = blockIdx.z;          // 0..7, each covers 256 keys
    const int tid = threadIdx.x, lane = tid & 31, warp = tid >> 5;
    const int wm = warp & 3, wn = warp >> 2;
    const int ql = q_len[b];

    const uint32_t baseQ = (uint32_t)__cvta_generic_to_shared(smem);
    const uint32_t baseK = baseQ + 65536u;

    #pragma unroll
    for (int i = 0; i < 2; i++) {
        int j = tid + i * 256;
        int h = j >> 6, r = j & 63;
        size_t idx = ((size_t)b * PH + h) * PLQ + q0 + r;
        sMM[j] = stats_m[idx];
        sIL[j] = 1.0f / stats_l[idx];
    }

    const __half* Qb = Qp + ((size_t)b * PLQ + q0) * PE;
    #pragma unroll
    for (int i = 0; i < 16; i++) {
        int f = tid + i * 256;
        int r = f >> 6, c = f & 63;
        uint32_t off = (uint32_t)r * 1024u + (uint32_t)((((c & 7) ^ (r & 7)) | (c & 56)) << 4);
        cpasync16(baseQ + off, Qb + (size_t)r * PE + c * 8);
    }
    cpcommit();

    const __half* Kbase = Kp + ((size_t)b * PLK + kz * 256) * PE;
    auto loadK = [&](int stage, int it) {
        int kt = it >> 3, h = it & 7;
        #pragma unroll
        for (int i = 0; i < 2; i++) {
            int f = tid + i * 256;
            int r = f >> 3, c = f & 7;
            cpasync16(baseK + stage * 8192u + (uint32_t)r * 128u + (uint32_t)((c ^ (r & 7)) << 4),
                      Kbase + (size_t)(kt * 64 + r) * PE + h * PHD + c * 8);
        }
        cpcommit();
    };
    loadK(0, 0);

    float acc[4][4];
    const int g = lane >> 2, tq = lane & 3;
    const int rr  = wm * 16 + g;
    const int rr8 = rr + 8;
    const bool v0 = (q0 + rr)  < ql;
    const bool v1 = (q0 + rr8) < ql;

    for (int it = 0; it < 32; it++) {
        const int kt = it >> 3, h = it & 7;
        if (h == 0) {
            #pragma unroll
            for (int ni = 0; ni < 4; ni++)
                #pragma unroll
                for (int j = 0; j < 4; j++) acc[ni][j] = 0.f;
        }
        if (it + 1 < 32) {
            loadK((it + 1) & 1, it + 1);
            asm volatile("cp.async.wait_group 1;");
        } else {
            asm volatile("cp.async.wait_group 0;");
        }
        __syncthreads();
        const uint32_t ko = (uint32_t)(it & 1) * 8192u;

        float d[4][4];
        #pragma unroll
        for (int ni = 0; ni < 4; ni++)
            #pragma unroll
            for (int j = 0; j < 4; j++) d[ni][j] = 0.f;

        #pragma unroll
        for (int ks = 0; ks < 4; ks++) {
            const int kb = ks * 16;
            uint32_t a[4], bb[4][2];
            {
                int r = wm * 16 + (lane & 15);
                int c = h * 8 + (kb >> 3) + (lane >> 4);
                uint32_t addr = baseQ + (uint32_t)r * 1024u + (uint32_t)((((c & 7) ^ (r & 7)) | (c & 56)) << 4);
                asm volatile("ldmatrix.sync.aligned.m8n8.x4.shared.b16 {%0,%1,%2,%3}, [%4];"
                             : "=r"(a[0]), "=r"(a[1]), "=r"(a[2]), "=r"(a[3]) : "r"(addr));
            }
            #pragma unroll
            for (int ni = 0; ni < 4; ni++) {
                int r  = wn * 32 + ni * 8 + (lane & 7);
                int ck = kb + (((lane >> 3) & 1) << 3);
                uint32_t addr = baseK + ko + (uint32_t)r * 128u + (uint32_t)((((ck >> 3) ^ (r & 7))) << 4);
                asm volatile("ldmatrix.sync.aligned.m8n8.x2.shared.b16 {%0,%1}, [%2];"
                             : "=r"(bb[ni][0]), "=r"(bb[ni][1]) : "r"(addr));
            }
            #pragma unroll
            for (int ni = 0; ni < 4; ni++) {
                asm volatile(
                    "mma.sync.aligned.m16n8k16.row.col.f32.f16.f16.f32 "
                    "{%0,%1,%2,%3}, {%4,%5,%6,%7}, {%8,%9}, {%0,%1,%2,%3};"
                    : "+f"(d[ni][0]), "+f"(d[ni][1]), "+f"(d[ni][2]), "+f"(d[ni][3])
                    : "r"(a[0]), "r"(a[1]), "r"(a[2]), "r"(a[3]),
                      "r"(bb[ni][0]), "r"(bb[ni][1]));
            }
        }

        {
            float m0 = sMM[h * 64 + rr],  i0 = sIL[h * 64 + rr];
            float m1 = sMM[h * 64 + rr8], i1 = sIL[h * 64 + rr8];
            #pragma unroll
            for (int ni = 0; ni < 4; ni++) {
                acc[ni][0] += __expf(d[ni][0] * 0.125f - m0) * i0;
                acc[ni][1] += __expf(d[ni][1] * 0.125f - m0) * i0;
                acc[ni][2] += __expf(d[ni][2] * 0.125f - m1) * i1;
                acc[ni][3] += __expf(d[ni][3] * 0.125f - m1) * i1;
            }
        }

        if (h == 7) {
            int kbase = kz * 256 + kt * 64;
            #pragma unroll
            for (int ni = 0; ni < 4; ni++) {
                int cc = kbase + wn * 32 + ni * 8 + tq * 2;
                float2 w0 = v0 ? make_float2(acc[ni][0] * 0.125f, acc[ni][1] * 0.125f)
                               : make_float2(0.f, 0.f);
                float2 w1 = v1 ? make_float2(acc[ni][2] * 0.125f, acc[ni][3] * 0.125f)
                               : make_float2(0.f, 0.f);
                *reinterpret_cast<float2*>(wout + ((size_t)b * PLQ + q0 + rr)  * PLK + cc) = w0;
                *reinterpret_cast<float2*>(wout + ((size_t)b * PLQ + q0 + rr8) * PLK + cc) = w1;
            }
        }
        __syncthreads();
    }
}

// ---------------------------------------------------------------------------
// Convert all 9 weight matrices fp32 -> fp16 in one launch
// ---------------------------------------------------------------------------
struct Ptr9 { const float* p[9]; };
__global__ void convert_w_kernel(Ptr9 ps, __half* __restrict__ out)
{
    int m = blockIdx.y;
    int i = (blockIdx.x * blockDim.x + threadIdx.x) * 4;
    float4 v = *reinterpret_cast<const float4*>(ps.p[m] + i);
    __half2* o = reinterpret_cast<__half2*>(out + (size_t)m * PE * PE + i);
    o[0] = __floats2half2_rn(v.x, v.y);
    o[1] = __floats2half2_rn(v.z, v.w);
}

__global__ void f32_to_f16_kernel(const float* __restrict__ in, __half* __restrict__ out, int n)
{
    int i = (blockIdx.x * blockDim.x + threadIdx.x) * 4;
    if (i >= n) return;
    float4 v = *reinterpret_cast<const float4*>(in + i);
    __half2* o = reinterpret_cast<__half2*>(out + i);
    o[0] = __floats2half2_rn(v.x, v.y);
    o[1] = __floats2half2_rn(v.z, v.w);
}

// ---------------------------------------------------------------------------
// Mask invalid query rows: out32/out16[r,:] = valid ? in : 0
// ---------------------------------------------------------------------------
__global__ void mask_rows_kernel(const float* __restrict__ in, float* __restrict__ out32,
                                 __half* __restrict__ out16, const int* __restrict__ q_len)
{
    int r = blockIdx.x;
    bool valid = (r % PLQ) < q_len[r / PLQ];
    const float4* src = reinterpret_cast<const float4*>(in + (size_t)r * PE);
    float4* dst = reinterpret_cast<float4*>(out32 + (size_t)r * PE);
    __half2* dh = reinterpret_cast<__half2*>(out16 + (size_t)r * PE);
    for (int c = threadIdx.x; c < PE / 4; c += blockDim.x) {
        float4 v = valid ? src[c] : make_float4(0.f, 0.f, 0.f, 0.f);
        dst[c] = v;
        dh[c * 2]     = __floats2half2_rn(v.x, v.y);
        dh[c * 2 + 1] = __floats2half2_rn(v.z, v.w);
    }
}

// ---------------------------------------------------------------------------
// out[r,:] = LN( silu(X + Y) )*g + b ; optional fp16 copy; optional zero rows
// ---------------------------------------------------------------------------
__global__ __launch_bounds__(128)
void add_silu_ln_kernel(const float* __restrict__ X, const float* __restrict__ Y,
                        const float* __restrict__ g, const float* __restrict__ bln,
                        float* __restrict__ out, __half* __restrict__ out16,
                        const int* __restrict__ q_len, int zero_invalid)
{
    constexpr int D = 512;
    int r = blockIdx.x;
    int tid = threadIdx.x;
    int c = tid * 4;

    float4 x = *reinterpret_cast<const float4*>(X + (size_t)r * D + c);
    float4 y = *reinterpret_cast<const float4*>(Y + (size_t)r * D + c);
    float v[4] = {x.x + y.x, x.y + y.y, x.z + y.z, x.w + y.w};

    float s[4], sum = 0.f, sumsq = 0.f;
    #pragma unroll
    for (int i = 0; i < 4; i++) {
        s[i] = v[i] / (1.0f + __expf(-v[i]));
        sum += s[i];
        sumsq += s[i] * s[i];
    }

    __shared__ float r1[128], r2[128];
    r1[tid] = sum; r2[tid] = sumsq; __syncthreads();
    for (int st = 64; st > 0; st >>= 1) {
        if (tid < st) { r1[tid] += r1[tid + st]; r2[tid] += r2[tid + st]; }
        __syncthreads();
    }
    float mu  = r1[0] * (1.0f / D);
    float var = r2[0] * (1.0f / D) - mu * mu;
    float rs  = rsqrtf(var + 1e-5f);

    bool zero = zero_invalid && ((r % PLQ) >= q_len[r / PLQ]);

    float4 gg = *reinterpret_cast<const float4*>(g + c);
    float4 bb = *reinterpret_cast<const float4*>(bln + c);
    float4 o;
    o.x = zero ? 0.f : (s[0] - mu) * rs * gg.x + bb.x;
    o.y = zero ? 0.f : (s[1] - mu) * rs * gg.y + bb.y;
    o.z = zero ? 0.f : (s[2] - mu) * rs * gg.z + bb.z;
    o.w = zero ? 0.f : (s[3] - mu) * rs * gg.w + bb.w;
    *reinterpret_cast<float4*>(out + (size_t)r * D + c) = o;
    if (out16) {
        __half2* oh = reinterpret_cast<__half2*>(out16 + (size_t)r * D + c);
        oh[0] = __floats2half2_rn(o.x, o.y);
        oh[1] = __floats2half2_rn(o.z, o.w);
    }
}

// ---------------------------------------------------------------------------
// Host launcher
// ---------------------------------------------------------------------------
static void launch_gemm(const __half* A, int lda,
                        const __half* Bm, int ldb,
                        float* C32, __half* C16, int ldc,
                        const float* bias, int M, int N, int K)
{
    dim3 grid(N / 128, M / 128, 1);
    hgemm3_kernel<<<grid, 256, 98304>>>(A, lda, Bm, ldb, C32, C16, ldc, bias, M, N, K);
}

extern "C" void kernel_launch(void* const* d_in, const int* in_sizes, int n_in,
                              void* d_out, int out_size)
{
    const float* queries = (const float*)d_in[0];
    const float* keys    = (const float*)d_in[1];
    const int*   q_len   = (const int*)  d_in[2];
    const float* cWq = (const float*)d_in[3];  const float* cbq = (const float*)d_in[4];
    const float* cWk = (const float*)d_in[5];  const float* cbk = (const float*)d_in[6];
    const float* cWv = (const float*)d_in[7];  const float* cbv = (const float*)d_in[8];
    const float* cWo = (const float*)d_in[9];  const float* cbo = (const float*)d_in[10];
    const float* sWq = (const float*)d_in[11]; const float* sbq = (const float*)d_in[12];
    const float* sWk = (const float*)d_in[13]; const float* sbk = (const float*)d_in[14];
    const float* sWv = (const float*)d_in[15]; const float* sbv = (const float*)d_in[16];
    const float* sWo = (const float*)d_in[17]; const float* sbo = (const float*)d_in[18];
    const float* Wf  = (const float*)d_in[19]; const float* bf  = (const float*)d_in[20];
    const float* g_cross = (const float*)d_in[21]; const float* b_cross = (const float*)d_in[22];
    const float* g_ffn   = (const float*)d_in[23]; const float* b_ffn   = (const float*)d_in[24];
    const float* g_self  = (const float*)d_in[25]; const float* b_self  = (const float*)d_in[26];

    float* out_q = (float*)d_out;
    float* out_w = out_q + (size_t)PB * PLQ * PHID;

    float *QM, *Pp, *X1, *Fb, *X2, *sm, *sl;
    __half *w16, *keys16, *QM16, *Qp16, *Kp16, *Vp16, *Op16, *X116, *X216;
    cudaGetSymbolAddress((void**)&QM,   g_QM);
    cudaGetSymbolAddress((void**)&Pp,   g_Pp);
    cudaGetSymbolAddress((void**)&X1,   g_X1);
    cudaGetSymbolAddress((void**)&Fb,   g_Fb);
    cudaGetSymbolAddress((void**)&X2,   g_X2);
    cudaGetSymbolAddress((void**)&sm,   g_sm);
    cudaGetSymbolAddress((void**)&sl,   g_sl);
    cudaGetSymbolAddress((void**)&w16,  g_w16);
    cudaGetSymbolAddress((void**)&keys16, g_keys16);
    cudaGetSymbolAddress((void**)&QM16, g_QM16);
    cudaGetSymbolAddress((void**)&Qp16, g_Qp16);
    cudaGetSymbolAddress((void**)&Kp16, g_Kp16);
    cudaGetSymbolAddress((void**)&Vp16, g_Vp16);
    cudaGetSymbolAddress((void**)&Op16, g_Op16);
    cudaGetSymbolAddress((void**)&X116, g_X116);
    cudaGetSymbolAddress((void**)&X216, g_X216);

    cudaFuncSetAttribute(hgemm3_kernel, cudaFuncAttributeMaxDynamicSharedMemorySize, 98304);
    cudaFuncSetAttribute(flash_kernel, cudaFuncAttributeMaxDynamicSharedMemorySize, 66304);
    cudaFuncSetAttribute(weights_flash_kernel, cudaFuncAttributeMaxDynamicSharedMemorySize, 86016);

    const int MQ = PB * PLQ;   // 4096
    const int MK = PB * PLK;   // 8192

    // 0) convert weights (one launch) + keys to fp16
    Ptr9 ps;
    ps.p[0] = cWq; ps.p[1] = cWk; ps.p[2] = cWv; ps.p[3] = cWo;
    ps.p[4] = sWq; ps.p[5] = sWk; ps.p[6] = sWv; ps.p[7] = sWo; ps.p[8] = Wf;
    convert_w_kernel<<<dim3(PE * PE / 1024, 9), 256>>>(ps, w16);
    f32_to_f16_kernel<<<(MK * PE) / 1024, 256>>>(keys, keys16, MK * PE);

    // 1) masked queries (fp32 + fp16)
    mask_rows_kernel<<<MQ, 128>>>(queries, QM, QM16, q_len);

    // 2) cross projections (fp16 out)
    launch_gemm(QM16,   PE, w16 + 0*PE*PE, PE, nullptr, Qp16, PE, cbq, MQ, PE, PE);
    launch_gemm(keys16, PE, w16 + 1*PE*PE, PE, nullptr, Kp16, PE, cbk, MK, PE, PE);
    launch_gemm(keys16, PE, w16 + 2*PE*PE, PE, nullptr, Vp16, PE, cbv, MK, PE, PE);

    // 3) fused cross attention -> Op16 (+ stats for weights)
    flash_kernel<<<dim3(PLQ / 64, PH, PB), 256, 66304>>>(
        Qp16, Kp16, Vp16, Op16, sm, sl, PLK, 0, q_len);

    // 4) attention weights output (head mean, invalid q rows zeroed)
    weights_flash_kernel<<<dim3(PLQ / 64, PB, 8), 256, 86016>>>(
        Qp16, Kp16, sm, sl, q_len, out_w);

    // 5) cross out-projection (fp32)
    launch_gemm(Op16, PE, w16 + 3*PE*PE, PE, Pp, nullptr, PE, cbo, MQ, PE, PE);

    // 6) x1 = LN(silu(cross + qm))
    add_silu_ln_kernel<<<MQ, 128>>>(Pp, QM, g_cross, b_cross, X1, X116, q_len, 0);

    // 7) FFN + LN
    launch_gemm(X116, PE, w16 + 8*PE*PE, PE, Fb, nullptr, PHID, bf, MQ, PHID, PE);
    add_silu_ln_kernel<<<MQ, 128>>>(X1, Fb, g_ffn, b_ffn, X2, X216, q_len, 0);

    // 8) self projections (fp16)
    launch_gemm(X216, PHID, w16 + 4*PE*PE, PHID, nullptr, Qp16, PHID, sbq, MQ, PHID, PHID);
    launch_gemm(X216, PHID, w16 + 5*PE*PE, PHID, nullptr, Kp16, PHID, sbk, MQ, PHID, PHID);
    launch_gemm(X216, PHID, w16 + 6*PE*PE, PHID, nullptr, Vp16, PHID, sbv, MQ, PHID, PHID);

    // 9) fused self attention (masked keys) -> Op16
    flash_kernel<<<dim3(PLQ / 64, PH, PB), 256, 66304>>>(
        Qp16, Kp16, Vp16, Op16, nullptr, nullptr, PLQ, 1, q_len);

    // 10) self out-projection (fp32)
    launch_gemm(Op16, PHID, w16 + 7*PE*PE, PHID, Pp, nullptr, PHID, sbo, MQ, PHID, PHID);

    // 11) final: out = LN(silu(x2 + so)), invalid rows zeroed
    add_silu_ln_kernel<<<MQ, 128>>>(X2, Pp, g_self, b_self, out_q, nullptr, q_len, 1);
}

// round 6
// speedup vs baseline: 6.1328x; 1.8682x over previous
#include <cuda_runtime.h>
#include <cuda_fp16.h>
#include <cstdint>
#include <cstddef>

// Problem constants
#define PB   4
#define PLQ  1024
#define PLK  2048
#define PE   512
#define PHID 512
#define PH   8
#define PHD  64

// ---------------------------------------------------------------------------
// Scratch (__device__ globals; no runtime allocation allowed)
// ---------------------------------------------------------------------------
__device__ float  g_QM[PB * PLQ * PE];
__device__ float  g_Pp[PB * PLQ * PE];
__device__ float  g_X1[PB * PLQ * PE];
__device__ float  g_Fb[PB * PLQ * PHID];
__device__ float  g_X2[PB * PLQ * PHID];

__device__ __half g_w16 [9 * PE * PE];
__device__ __half g_keys16[PB * PLK * PE];
__device__ __half g_QM16 [PB * PLQ * PE];
__device__ __half g_Qp16 [PB * PLK * PE];
__device__ __half g_Kp16 [PB * PLK * PE];
__device__ __half g_Vp16 [PB * PLK * PE];
__device__ __half g_Op16 [PB * PLQ * PE];
__device__ __half g_X116 [PB * PLQ * PE];
__device__ __half g_X216 [PB * PLQ * PE];

__device__ float  g_sm[PB * PH * PLQ];
__device__ float  g_sl[PB * PH * PLQ];

// ---------------------------------------------------------------------------
// cp.async helpers
// ---------------------------------------------------------------------------
__device__ __forceinline__ void cpasync16(uint32_t dst, const void* src) {
    asm volatile("cp.async.cg.shared.global [%0], [%1], 16;" :: "r"(dst), "l"(src));
}
__device__ __forceinline__ void cpcommit() {
    asm volatile("cp.async.commit_group;");
}
__device__ __forceinline__ uint32_t packh2(float a, float b) {
    __half2 h = __floats2half2_rn(a, b);
    return *reinterpret_cast<uint32_t*>(&h);
}

// ---------------------------------------------------------------------------
// 3-stage pipelined tensor-core HGEMM: C = (A @ B^T + bias) * outscale
//   A [M,K] f16 row-major, B [N,K] f16 row-major, C f32 and/or f16.
// CTA tile 128x128x64; 8 warps 2(M)x4(N); warp 64x32.
// Dynamic smem: sA 3*16KB @0, sB 3*16KB @49152; total 98304.
// ---------------------------------------------------------------------------
__global__ __launch_bounds__(256)
void hgemm3_kernel(const __half* __restrict__ A, int lda,
                   const __half* __restrict__ Bm, int ldb,
                   float* __restrict__ C32, __half* __restrict__ C16,
                   int ldc, const float* __restrict__ bias,
                   int M, int N, int K, float outscale)
{
    extern __shared__ char smem[];
    const uint32_t baseA = (uint32_t)__cvta_generic_to_shared(smem);
    const uint32_t baseB = baseA + 49152u;

    const int tid  = threadIdx.x;
    const int lane = tid & 31;
    const int warp = tid >> 5;
    const int wm   = warp >> 2;
    const int wn   = warp & 3;
    const int m0   = blockIdx.y * 128;
    const int n0   = blockIdx.x * 128;

    auto load_tile = [&](int stage, int k0) {
        #pragma unroll
        for (int i = 0; i < 4; i++) {
            int f = tid + i * 256;
            int r = f >> 3, c = f & 7;
            cpasync16(baseA + (uint32_t)stage * 16384u + (uint32_t)r * 128u + (uint32_t)((c ^ (r & 7)) << 4),
                      A + (size_t)(m0 + r) * lda + k0 + c * 8);
        }
        #pragma unroll
        for (int i = 0; i < 4; i++) {
            int f = tid + i * 256;
            int r = f >> 3, c = f & 7;
            cpasync16(baseB + (uint32_t)stage * 16384u + (uint32_t)r * 128u + (uint32_t)((c ^ (r & 7)) << 4),
                      Bm + (size_t)(n0 + r) * ldb + k0 + c * 8);
        }
        cpcommit();
    };

    float d[4][4][4];
    #pragma unroll
    for (int mi = 0; mi < 4; mi++)
        #pragma unroll
        for (int ni = 0; ni < 4; ni++)
            #pragma unroll
            for (int j = 0; j < 4; j++) d[mi][ni][j] = 0.f;

    const int nt = K >> 6;
    load_tile(0, 0);
    if (nt > 1) load_tile(1, 64);

    for (int t = 0; t < nt; t++) {
        if (t < nt - 1) { asm volatile("cp.async.wait_group 1;"); }
        else            { asm volatile("cp.async.wait_group 0;"); }
        __syncthreads();
        if (t + 2 < nt) load_tile((t + 2) % 3, (t + 2) << 6);

        const uint32_t stA = baseA + (uint32_t)(t % 3) * 16384u;
        const uint32_t stB = baseB + (uint32_t)(t % 3) * 16384u;

        #pragma unroll
        for (int ks = 0; ks < 4; ks++) {
            const int kb = ks * 16;
            uint32_t a[4][4], b[4][2];
            #pragma unroll
            for (int mi = 0; mi < 4; mi++) {
                int r  = wm * 64 + mi * 16 + (lane & 15);
                int ck = kb + ((lane >> 4) << 3);
                uint32_t addr = stA + (uint32_t)r * 128u + (uint32_t)((((ck >> 3) ^ (r & 7))) << 4);
                asm volatile("ldmatrix.sync.aligned.m8n8.x4.shared.b16 {%0,%1,%2,%3}, [%4];"
                             : "=r"(a[mi][0]), "=r"(a[mi][1]), "=r"(a[mi][2]), "=r"(a[mi][3])
                             : "r"(addr));
            }
            #pragma unroll
            for (int ni = 0; ni < 4; ni++) {
                int r  = wn * 32 + ni * 8 + (lane & 7);
                int ck = kb + (((lane >> 3) & 1) << 3);
                uint32_t addr = stB + (uint32_t)r * 128u + (uint32_t)((((ck >> 3) ^ (r & 7))) << 4);
                asm volatile("ldmatrix.sync.aligned.m8n8.x2.shared.b16 {%0,%1}, [%2];"
                             : "=r"(b[ni][0]), "=r"(b[ni][1])
                             : "r"(addr));
            }
            #pragma unroll
            for (int mi = 0; mi < 4; mi++)
                #pragma unroll
                for (int ni = 0; ni < 4; ni++) {
                    asm volatile(
                        "mma.sync.aligned.m16n8k16.row.col.f32.f16.f16.f32 "
                        "{%0,%1,%2,%3}, {%4,%5,%6,%7}, {%8,%9}, {%0,%1,%2,%3};"
                        : "+f"(d[mi][ni][0]), "+f"(d[mi][ni][1]),
                          "+f"(d[mi][ni][2]), "+f"(d[mi][ni][3])
                        : "r"(a[mi][0]), "r"(a[mi][1]), "r"(a[mi][2]), "r"(a[mi][3]),
                          "r"(b[ni][0]), "r"(b[ni][1]));
                }
        }
        __syncthreads();
    }

    const int g = lane >> 2, tq = lane & 3;
    #pragma unroll
    for (int mi = 0; mi < 4; mi++) {
        #pragma unroll
        for (int ni = 0; ni < 4; ni++) {
            int rr = m0 + wm * 64 + mi * 16 + g;
            int cc = n0 + wn * 32 + ni * 8 + tq * 2;
            float b0 = 0.f, b1 = 0.f;
            if (bias) { b0 = bias[cc]; b1 = bias[cc + 1]; }
            float o00 = (d[mi][ni][0] + b0) * outscale, o01 = (d[mi][ni][1] + b1) * outscale;
            float o10 = (d[mi][ni][2] + b0) * outscale, o11 = (d[mi][ni][3] + b1) * outscale;
            if (C32) {
                *reinterpret_cast<float2*>(C32 + (size_t)rr * ldc + cc)       = make_float2(o00, o01);
                *reinterpret_cast<float2*>(C32 + (size_t)(rr + 8) * ldc + cc) = make_float2(o10, o11);
            }
            if (C16) {
                *reinterpret_cast<__half2*>(C16 + (size_t)rr * ldc + cc)       = __floats2half2_rn(o00, o01);
                *reinterpret_cast<__half2*>(C16 + (size_t)(rr + 8) * ldc + cc) = __floats2half2_rn(o10, o11);
            }
        }
    }
}

// ---------------------------------------------------------------------------
// FA2-style fused flash attention. 128 threads (4 warps), q-tile 64 rows.
// Warp w owns rows w*16..w*16+15; per-warp S fragment = m16 x n64.
// In-register online softmax; S C-fragments repacked directly as P A-fragments.
// Q is PRESCALED by 1/8 upstream. Early exit if q0 >= q_len[b].
// Dynamic smem: sQ 0..8192 | sK 8192..24576 (2 stg) | sV 24576..40960 (2 stg)
// ---------------------------------------------------------------------------
__global__ __launch_bounds__(128)
void flash2_kernel(const __half* __restrict__ Q, const __half* __restrict__ K,
                   const __half* __restrict__ V, __half* __restrict__ O,
                   float* __restrict__ stats_m, float* __restrict__ stats_l,
                   int LK, int masked, const int* __restrict__ q_len)
{
    extern __shared__ char smem[];
    const int b = blockIdx.z, h = blockIdx.y, q0 = blockIdx.x * 64;
    const int ql = q_len[b];
    if (q0 >= ql) return;                 // invalid q rows never reach outputs

    const int tid = threadIdx.x, lane = tid & 31, warp = tid >> 5;
    const int limit = masked ? ql : LK;
    const int nt = (limit + 63) >> 6;

    const uint32_t baseQ = (uint32_t)__cvta_generic_to_shared(smem);
    const uint32_t baseK = baseQ + 8192u;
    const uint32_t baseV = baseQ + 24576u;

    const __half* Qb = Q + ((size_t)b * PLQ + q0) * PE + h * PHD;
    const __half* Kb = K + ((size_t)b * LK) * PE + h * PHD;
    const __half* Vb = V + ((size_t)b * LK) * PE + h * PHD;

    // Q: 64 rows x 8 chunks = 512, 4/thread (no commit; joins group of loadKV(0))
    #pragma unroll
    for (int i = 0; i < 4; i++) {
        int f = tid + i * 128;
        int r = f >> 3, c = f & 7;
        cpasync16(baseQ + (uint32_t)r * 128u + (uint32_t)((c ^ (r & 7)) << 4),
                  Qb + (size_t)r * PE + c * 8);
    }
    auto loadKV = [&](int stage, int k0) {
        #pragma unroll
        for (int i = 0; i < 4; i++) {
            int f = tid + i * 128;
            int r = f >> 3, c = f & 7;
            cpasync16(baseK + stage * 8192u + (uint32_t)r * 128u + (uint32_t)((c ^ (r & 7)) << 4),
                      Kb + (size_t)(k0 + r) * PE + c * 8);
        }
        #pragma unroll
        for (int i = 0; i < 4; i++) {
            int f = tid + i * 128;
            int r = f >> 3, c = f & 7;
            cpasync16(baseV + stage * 8192u + (uint32_t)r * 128u + (uint32_t)((c ^ (r & 7)) << 4),
                      Vb + (size_t)(k0 + r) * PE + c * 8);
        }
        cpcommit();
    };
    loadKV(0, 0);

    float m0 = -3.0e38f, m1 = -3.0e38f, l0 = 0.f, l1 = 0.f;
    float o[8][4];
    #pragma unroll
    for (int ni = 0; ni < 8; ni++)
        #pragma unroll
        for (int j = 0; j < 4; j++) o[ni][j] = 0.f;

    for (int t = 0; t < nt; t++) {
        if (t + 1 < nt) {
            loadKV((t + 1) & 1, (t + 1) << 6);
            asm volatile("cp.async.wait_group 1;");
        } else {
            asm volatile("cp.async.wait_group 0;");
        }
        __syncthreads();
        const uint32_t kvo = (uint32_t)(t & 1) * 8192u;

        // ---- S (16x64 per warp) ----
        float d[8][4];
        #pragma unroll
        for (int ni = 0; ni < 8; ni++)
            #pragma unroll
            for (int j = 0; j < 4; j++) d[ni][j] = 0.f;

        #pragma unroll
        for (int ks = 0; ks < 4; ks++) {
            const int kb = ks * 16;
            uint32_t a[4];
            {
                int r  = warp * 16 + (lane & 15);
                int ck = kb + ((lane >> 4) << 3);
                uint32_t addr = baseQ + (uint32_t)r * 128u + (uint32_t)((((ck >> 3) ^ (r & 7))) << 4);
                asm volatile("ldmatrix.sync.aligned.m8n8.x4.shared.b16 {%0,%1,%2,%3}, [%4];"
                             : "=r"(a[0]), "=r"(a[1]), "=r"(a[2]), "=r"(a[3]) : "r"(addr));
            }
            #pragma unroll
            for (int ni = 0; ni < 8; ni++) {
                uint32_t b0, b1;
                int r  = ni * 8 + (lane & 7);
                int ck = kb + (((lane >> 3) & 1) << 3);
                uint32_t addr = baseK + kvo + (uint32_t)r * 128u + (uint32_t)((((ck >> 3) ^ (r & 7))) << 4);
                asm volatile("ldmatrix.sync.aligned.m8n8.x2.shared.b16 {%0,%1}, [%2];"
                             : "=r"(b0), "=r"(b1) : "r"(addr));
                asm volatile(
                    "mma.sync.aligned.m16n8k16.row.col.f32.f16.f16.f32 "
                    "{%0,%1,%2,%3}, {%4,%5,%6,%7}, {%8,%9}, {%0,%1,%2,%3};"
                    : "+f"(d[ni][0]), "+f"(d[ni][1]), "+f"(d[ni][2]), "+f"(d[ni][3])
                    : "r"(a[0]), "r"(a[1]), "r"(a[2]), "r"(a[3]), "r"(b0), "r"(b1));
            }
        }

        // ---- in-register online softmax (rows g, g+8 of this warp) ----
        const int k0 = t << 6;
        const bool doMask = masked && (k0 + 64 > limit);
        float t0 = -3.0e38f, t1 = -3.0e38f;
        #pragma unroll
        for (int ni = 0; ni < 8; ni++) {
            if (doMask) {
                int c0 = k0 + ni * 8 + (lane & 3) * 2;
                if (c0 >= limit)     { d[ni][0] = -3.0e38f; d[ni][2] = -3.0e38f; }
                if (c0 + 1 >= limit) { d[ni][1] = -3.0e38f; d[ni][3] = -3.0e38f; }
            }
            t0 = fmaxf(t0, fmaxf(d[ni][0], d[ni][1]));
            t1 = fmaxf(t1, fmaxf(d[ni][2], d[ni][3]));
        }
        t0 = fmaxf(t0, __shfl_xor_sync(0xffffffffu, t0, 1));
        t0 = fmaxf(t0, __shfl_xor_sync(0xffffffffu, t0, 2));
        t1 = fmaxf(t1, __shfl_xor_sync(0xffffffffu, t1, 1));
        t1 = fmaxf(t1, __shfl_xor_sync(0xffffffffu, t1, 2));
        float mn0 = fmaxf(m0, t0), mn1 = fmaxf(m1, t1);
        float fr0 = __expf(m0 - mn0), fr1 = __expf(m1 - mn1);
        m0 = mn0; m1 = mn1;

        float s0 = 0.f, s1 = 0.f;
        uint32_t pf[8][2];
        #pragma unroll
        for (int ni = 0; ni < 8; ni++) {
            float e0 = __expf(d[ni][0] - mn0), e1 = __expf(d[ni][1] - mn0);
            float e2 = __expf(d[ni][2] - mn1), e3 = __expf(d[ni][3] - mn1);
            s0 += e0 + e1; s1 += e2 + e3;
            pf[ni][0] = packh2(e0, e1);
            pf[ni][1] = packh2(e2, e3);
        }
        s0 += __shfl_xor_sync(0xffffffffu, s0, 1);
        s0 += __shfl_xor_sync(0xffffffffu, s0, 2);
        s1 += __shfl_xor_sync(0xffffffffu, s1, 1);
        s1 += __shfl_xor_sync(0xffffffffu, s1, 2);
        l0 = l0 * fr0 + s0;
        l1 = l1 * fr1 + s1;
        #pragma unroll
        for (int ni = 0; ni < 8; ni++) {
            o[ni][0] *= fr0; o[ni][1] *= fr0;
            o[ni][2] *= fr1; o[ni][3] *= fr1;
        }

        // ---- O += P @ V : P A-fragments direct from pf ----
        #pragma unroll
        for (int j = 0; j < 4; j++) {
            uint32_t a0 = pf[2 * j][0], a1 = pf[2 * j][1];
            uint32_t a2 = pf[2 * j + 1][0], a3 = pf[2 * j + 1][1];
            #pragma unroll
            for (int ni = 0; ni < 8; ni++) {
                uint32_t b0, b1;
                int r = j * 16 + (lane & 15);
                uint32_t addr = baseV + kvo + (uint32_t)r * 128u + (uint32_t)(((ni ^ (r & 7))) << 4);
                asm volatile("ldmatrix.sync.aligned.m8n8.x2.trans.shared.b16 {%0,%1}, [%2];"
                             : "=r"(b0), "=r"(b1) : "r"(addr));
                asm volatile(
                    "mma.sync.aligned.m16n8k16.row.col.f32.f16.f16.f32 "
                    "{%0,%1,%2,%3}, {%4,%5,%6,%7}, {%8,%9}, {%0,%1,%2,%3};"
                    : "+f"(o[ni][0]), "+f"(o[ni][1]), "+f"(o[ni][2]), "+f"(o[ni][3])
                    : "r"(a0), "r"(a1), "r"(a2), "r"(a3), "r"(b0), "r"(b1));
            }
        }
        __syncthreads();
    }

    // ---- epilogue ----
    const int g = lane >> 2, tq = lane & 3;
    const int r0 = warp * 16 + g;
    float il0 = 1.0f / l0, il1 = 1.0f / l1;
    __half* Ob = O + ((size_t)b * PLQ + q0) * PE + h * PHD;
    #pragma unroll
    for (int ni = 0; ni < 8; ni++) {
        int cc = ni * 8 + tq * 2;
        *reinterpret_cast<__half2*>(Ob + (size_t)r0 * PE + cc) =
            __floats2half2_rn(o[ni][0] * il0, o[ni][1] * il0);
        *reinterpret_cast<__half2*>(Ob + (size_t)(r0 + 8) * PE + cc) =
            __floats2half2_rn(o[ni][2] * il1, o[ni][3] * il1);
    }
    if (stats_m && tq == 0) {
        size_t idx = ((size_t)b * PH + h) * PLQ + q0 + r0;
        stats_m[idx] = m0;  stats_l[idx] = l0;
        stats_m[idx + 8] = m1;  stats_l[idx + 8] = l1;
    }
}

// ---------------------------------------------------------------------------
// Weights output: per CTA one (b, 64-row q-tile, 1/8 of k range = 256 keys).
// Q prescaled by 1/8; stats (m,l) from flash. Early exit: invalid tiles -> 0.
// Dynamic smem: sQ 0..65536 | sK 65536..81920 (2 stg) | sMM 81920 | sIL 83968
// ---------------------------------------------------------------------------
__global__ __launch_bounds__(256)
void weights_flash_kernel(const __half* __restrict__ Qp, const __half* __restrict__ Kp,
                          const float* __restrict__ stats_m, const float* __restrict__ stats_l,
                          const int* __restrict__ q_len, float* __restrict__ wout)
{
    extern __shared__ char smem[];
    float* sMM = reinterpret_cast<float*>(smem + 81920);
    float* sIL = reinterpret_cast<float*>(smem + 83968);

    const int q0 = blockIdx.x * 64;
    const int b  = blockIdx.y;
    const int kz = blockIdx.z;
    const int tid = threadIdx.x, lane = tid & 31, warp = tid >> 5;
    const int wm = warp & 3, wn = warp >> 2;
    const int ql = q_len[b];

    if (q0 >= ql) {   // whole tile invalid -> zeros
        #pragma unroll
        for (int i = 0; i < 16; i++) {
            int f = tid + i * 256;
            int r = f >> 6, c = (f & 63) * 4;
            *reinterpret_cast<float4*>(wout + ((size_t)b * PLQ + q0 + r) * PLK + kz * 256 + c) =
                make_float4(0.f, 0.f, 0.f, 0.f);
        }
        return;
    }

    const uint32_t baseQ = (uint32_t)__cvta_generic_to_shared(smem);
    const uint32_t baseK = baseQ + 65536u;

    #pragma unroll
    for (int i = 0; i < 2; i++) {
        int j = tid + i * 256;
        int h = j >> 6, r = j & 63;
        size_t idx = ((size_t)b * PH + h) * PLQ + q0 + r;
        sMM[j] = stats_m[idx];
        sIL[j] = 1.0f / stats_l[idx];
    }

    const __half* Qb = Qp + ((size_t)b * PLQ + q0) * PE;
    #pragma unroll
    for (int i = 0; i < 16; i++) {
        int f = tid + i * 256;
        int r = f >> 6, c = f & 63;
        uint32_t off = (uint32_t)r * 1024u + (uint32_t)((((c & 7) ^ (r & 7)) | (c & 56)) << 4);
        cpasync16(baseQ + off, Qb + (size_t)r * PE + c * 8);
    }
    cpcommit();

    const __half* Kbase = Kp + ((size_t)b * PLK + kz * 256) * PE;
    auto loadK = [&](int stage, int it) {
        int kt = it >> 3, h = it & 7;
        #pragma unroll
        for (int i = 0; i < 2; i++) {
            int f = tid + i * 256;
            int r = f >> 3, c = f & 7;
            cpasync16(baseK + stage * 8192u + (uint32_t)r * 128u + (uint32_t)((c ^ (r & 7)) << 4),
                      Kbase + (size_t)(kt * 64 + r) * PE + h * PHD + c * 8);
        }
        cpcommit();
    };
    loadK(0, 0);

    float acc[4][4];
    const int g = lane >> 2, tq = lane & 3;
    const int rr  = wm * 16 + g;
    const int rr8 = rr + 8;
    const bool v0 = (q0 + rr)  < ql;
    const bool v1 = (q0 + rr8) < ql;

    for (int it = 0; it < 32; it++) {
        const int kt = it >> 3, h = it & 7;
        if (h == 0) {
            #pragma unroll
            for (int ni = 0; ni < 4; ni++)
                #pragma unroll
                for (int j = 0; j < 4; j++) acc[ni][j] = 0.f;
        }
        if (it + 1 < 32) {
            loadK((it + 1) & 1, it + 1);
            asm volatile("cp.async.wait_group 1;");
        } else {
            asm volatile("cp.async.wait_group 0;");
        }
        __syncthreads();
        const uint32_t ko = (uint32_t)(it & 1) * 8192u;

        float d[4][4];
        #pragma unroll
        for (int ni = 0; ni < 4; ni++)
            #pragma unroll
            for (int j = 0; j < 4; j++) d[ni][j] = 0.f;

        #pragma unroll
        for (int ks = 0; ks < 4; ks++) {
            const int kb = ks * 16;
            uint32_t a[4], bb[4][2];
            {
                int r = wm * 16 + (lane & 15);
                int c = h * 8 + (kb >> 3) + (lane >> 4);
                uint32_t addr = baseQ + (uint32_t)r * 1024u + (uint32_t)((((c & 7) ^ (r & 7)) | (c & 56)) << 4);
                asm volatile("ldmatrix.sync.aligned.m8n8.x4.shared.b16 {%0,%1,%2,%3}, [%4];"
                             : "=r"(a[0]), "=r"(a[1]), "=r"(a[2]), "=r"(a[3]) : "r"(addr));
            }
            #pragma unroll
            for (int ni = 0; ni < 4; ni++) {
                int r  = wn * 32 + ni * 8 + (lane & 7);
                int ck = kb + (((lane >> 3) & 1) << 3);
                uint32_t addr = baseK + ko + (uint32_t)r * 128u + (uint32_t)((((ck >> 3) ^ (r & 7))) << 4);
                asm volatile("ldmatrix.sync.aligned.m8n8.x2.shared.b16 {%0,%1}, [%2];"
                             : "=r"(bb[ni][0]), "=r"(bb[ni][1]) : "r"(addr));
            }
            #pragma unroll
            for (int ni = 0; ni < 4; ni++) {
                asm volatile(
                    "mma.sync.aligned.m16n8k16.row.col.f32.f16.f16.f32 "
                    "{%0,%1,%2,%3}, {%4,%5,%6,%7}, {%8,%9}, {%0,%1,%2,%3};"
                    : "+f"(d[ni][0]), "+f"(d[ni][1]), "+f"(d[ni][2]), "+f"(d[ni][3])
                    : "r"(a[0]), "r"(a[1]), "r"(a[2]), "r"(a[3]),
                      "r"(bb[ni][0]), "r"(bb[ni][1]));
            }
        }

        {
            float mm0 = sMM[h * 64 + rr],  i0 = sIL[h * 64 + rr];
            float mm1 = sMM[h * 64 + rr8], i1 = sIL[h * 64 + rr8];
            #pragma unroll
            for (int ni = 0; ni < 4; ni++) {
                acc[ni][0] += __expf(d[ni][0] - mm0) * i0;
                acc[ni][1] += __expf(d[ni][1] - mm0) * i0;
                acc[ni][2] += __expf(d[ni][2] - mm1) * i1;
                acc[ni][3] += __expf(d[ni][3] - mm1) * i1;
            }
        }

        if (h == 7) {
            int kbase = kz * 256 + kt * 64;
            #pragma unroll
            for (int ni = 0; ni < 4; ni++) {
                int cc = kbase + wn * 32 + ni * 8 + tq * 2;
                float2 w0 = v0 ? make_float2(acc[ni][0] * 0.125f, acc[ni][1] * 0.125f)
                               : make_float2(0.f, 0.f);
                float2 w1 = v1 ? make_float2(acc[ni][2] * 0.125f, acc[ni][3] * 0.125f)
                               : make_float2(0.f, 0.f);
                *reinterpret_cast<float2*>(wout + ((size_t)b * PLQ + q0 + rr)  * PLK + cc) = w0;
                *reinterpret_cast<float2*>(wout + ((size_t)b * PLQ + q0 + rr8) * PLK + cc) = w1;
            }
        }
        __syncthreads();
    }
}

// ---------------------------------------------------------------------------
// Converts / elementwise
// ---------------------------------------------------------------------------
struct Ptr9 { const float* p[9]; };
__global__ void convert_w_kernel(Ptr9 ps, __half* __restrict__ out)
{
    int m = blockIdx.y;
    int i = (blockIdx.x * blockDim.x + threadIdx.x) * 4;
    float4 v = *reinterpret_cast<const float4*>(ps.p[m] + i);
    __half2* o = reinterpret_cast<__half2*>(out + (size_t)m * PE * PE + i);
    o[0] = __floats2half2_rn(v.x, v.y);
    o[1] = __floats2half2_rn(v.z, v.w);
}

__global__ void f32_to_f16_kernel(const float* __restrict__ in, __half* __restrict__ out, int n)
{
    int i = (blockIdx.x * blockDim.x + threadIdx.x) * 4;
    if (i >= n) return;
    float4 v = *reinterpret_cast<const float4*>(in + i);
    __half2* o = reinterpret_cast<__half2*>(out + i);
    o[0] = __floats2half2_rn(v.x, v.y);
    o[1] = __floats2half2_rn(v.z, v.w);
}

__global__ void mask_rows_kernel(const float* __restrict__ in, float* __restrict__ out32,
                                 __half* __restrict__ out16, const int* __restrict__ q_len)
{
    int r = blockIdx.x;
    bool valid = (r % PLQ) < q_len[r / PLQ];
    const float4* src = reinterpret_cast<const float4*>(in + (size_t)r * PE);
    float4* dst = reinterpret_cast<float4*>(out32 + (size_t)r * PE);
    __half2* dh = reinterpret_cast<__half2*>(out16 + (size_t)r * PE);
    for (int c = threadIdx.x; c < PE / 4; c += blockDim.x) {
        float4 v = valid ? src[c] : make_float4(0.f, 0.f, 0.f, 0.f);
        dst[c] = v;
        dh[c * 2]     = __floats2half2_rn(v.x, v.y);
        dh[c * 2 + 1] = __floats2half2_rn(v.z, v.w);
    }
}

__global__ __launch_bounds__(128)
void add_silu_ln_kernel(const float* __restrict__ X, const float* __restrict__ Y,
                        const float* __restrict__ g, const float* __restrict__ bln,
                        float* __restrict__ out, __half* __restrict__ out16,
                        const int* __restrict__ q_len, int zero_invalid)
{
    constexpr int D = 512;
    int r = blockIdx.x;
    int tid = threadIdx.x;
    int c = tid * 4;

    float4 x = *reinterpret_cast<const float4*>(X + (size_t)r * D + c);
    float4 y = *reinterpret_cast<const float4*>(Y + (size_t)r * D + c);
    float v[4] = {x.x + y.x, x.y + y.y, x.z + y.z, x.w + y.w};

    float s[4], sum = 0.f, sumsq = 0.f;
    #pragma unroll
    for (int i = 0; i < 4; i++) {
        s[i] = v[i] / (1.0f + __expf(-v[i]));
        sum += s[i];
        sumsq += s[i] * s[i];
    }

    __shared__ float r1[128], r2[128];
    r1[tid] = sum; r2[tid] = sumsq; __syncthreads();
    for (int st = 64; st > 0; st >>= 1) {
        if (tid < st) { r1[tid] += r1[tid + st]; r2[tid] += r2[tid + st]; }
        __syncthreads();
    }
    float mu  = r1[0] * (1.0f / D);
    float var = r2[0] * (1.0f / D) - mu * mu;
    float rs  = rsqrtf(var + 1e-5f);

    bool zero = zero_invalid && ((r % PLQ) >= q_len[r / PLQ]);

    float4 gg = *reinterpret_cast<const float4*>(g + c);
    float4 bb = *reinterpret_cast<const float4*>(bln + c);
    float4 o;
    o.x = zero ? 0.f : (s[0] - mu) * rs * gg.x + bb.x;
    o.y = zero ? 0.f : (s[1] - mu) * rs * gg.y + bb.y;
    o.z = zero ? 0.f : (s[2] - mu) * rs * gg.z + bb.z;
    o.w = zero ? 0.f : (s[3] - mu) * rs * gg.w + bb.w;
    *reinterpret_cast<float4*>(out + (size_t)r * D + c) = o;
    if (out16) {
        __half2* oh = reinterpret_cast<__half2*>(out16 + (size_t)r * D + c);
        oh[0] = __floats2half2_rn(o.x, o.y);
        oh[1] = __floats2half2_rn(o.z, o.w);
    }
}

// ---------------------------------------------------------------------------
// Host launcher
// ---------------------------------------------------------------------------
static void launch_gemm(const __half* A, int lda,
                        const __half* Bm, int ldb,
                        float* C32, __half* C16, int ldc,
                        const float* bias, int M, int N, int K, float outscale = 1.0f)
{
    dim3 grid(N / 128, M / 128, 1);
    hgemm3_kernel<<<grid, 256, 98304>>>(A, lda, Bm, ldb, C32, C16, ldc, bias, M, N, K, outscale);
}

extern "C" void kernel_launch(void* const* d_in, const int* in_sizes, int n_in,
                              void* d_out, int out_size)
{
    const float* queries = (const float*)d_in[0];
    const float* keys    = (const float*)d_in[1];
    const int*   q_len   = (const int*)  d_in[2];
    const float* cWq = (const float*)d_in[3];  const float* cbq = (const float*)d_in[4];
    const float* cWk = (const float*)d_in[5];  const float* cbk = (const float*)d_in[6];
    const float* cWv = (const float*)d_in[7];  const float* cbv = (const float*)d_in[8];
    const float* cWo = (const float*)d_in[9];  const float* cbo = (const float*)d_in[10];
    const float* sWq = (const float*)d_in[11]; const float* sbq = (const float*)d_in[12];
    const float* sWk = (const float*)d_in[13]; const float* sbk = (const float*)d_in[14];
    const float* sWv = (const float*)d_in[15]; const float* sbv = (const float*)d_in[16];
    const float* sWo = (const float*)d_in[17]; const float* sbo = (const float*)d_in[18];
    const float* Wf  = (const float*)d_in[19]; const float* bf  = (const float*)d_in[20];
    const float* g_cross = (const float*)d_in[21]; const float* b_cross = (const float*)d_in[22];
    const float* g_ffn   = (const float*)d_in[23]; const float* b_ffn   = (const float*)d_in[24];
    const float* g_self  = (const float*)d_in[25]; const float* b_self  = (const float*)d_in[26];

    float* out_q = (float*)d_out;
    float* out_w = out_q + (size_t)PB * PLQ * PHID;

    float *QM, *Pp, *X1, *Fb, *X2, *sm, *sl;
    __half *w16, *keys16, *QM16, *Qp16, *Kp16, *Vp16, *Op16, *X116, *X216;
    cudaGetSymbolAddress((void**)&QM,   g_QM);
    cudaGetSymbolAddress((void**)&Pp,   g_Pp);
    cudaGetSymbolAddress((void**)&X1,   g_X1);
    cudaGetSymbolAddress((void**)&Fb,   g_Fb);
    cudaGetSymbolAddress((void**)&X2,   g_X2);
    cudaGetSymbolAddress((void**)&sm,   g_sm);
    cudaGetSymbolAddress((void**)&sl,   g_sl);
    cudaGetSymbolAddress((void**)&w16,  g_w16);
    cudaGetSymbolAddress((void**)&keys16, g_keys16);
    cudaGetSymbolAddress((void**)&QM16, g_QM16);
    cudaGetSymbolAddress((void**)&Qp16, g_Qp16);
    cudaGetSymbolAddress((void**)&Kp16, g_Kp16);
    cudaGetSymbolAddress((void**)&Vp16, g_Vp16);
    cudaGetSymbolAddress((void**)&Op16, g_Op16);
    cudaGetSymbolAddress((void**)&X116, g_X116);
    cudaGetSymbolAddress((void**)&X216, g_X216);

    cudaFuncSetAttribute(hgemm3_kernel, cudaFuncAttributeMaxDynamicSharedMemorySize, 98304);
    cudaFuncSetAttribute(flash2_kernel, cudaFuncAttributeMaxDynamicSharedMemorySize, 40960);
    cudaFuncSetAttribute(weights_flash_kernel, cudaFuncAttributeMaxDynamicSharedMemorySize, 86016);

    const int MQ = PB * PLQ;   // 4096
    const int MK = PB * PLK;   // 8192

    // 0) convert weights + keys to fp16
    Ptr9 ps;
    ps.p[0] = cWq; ps.p[1] = cWk; ps.p[2] = cWv; ps.p[3] = cWo;
    ps.p[4] = sWq; ps.p[5] = sWk; ps.p[6] = sWv; ps.p[7] = sWo; ps.p[8] = Wf;
    convert_w_kernel<<<dim3(PE * PE / 1024, 9), 256>>>(ps, w16);
    f32_to_f16_kernel<<<(MK * PE) / 1024, 256>>>(keys, keys16, MK * PE);

    // 1) masked queries
    mask_rows_kernel<<<MQ, 128>>>(queries, QM, QM16, q_len);

    // 2) cross projections (Q prescaled by 1/8)
    launch_gemm(QM16,   PE, w16 + 0*PE*PE, PE, nullptr, Qp16, PE, cbq, MQ, PE, PE, 0.125f);
    launch_gemm(keys16, PE, w16 + 1*PE*PE, PE, nullptr, Kp16, PE, cbk, MK, PE, PE);
    launch_gemm(keys16, PE, w16 + 2*PE*PE, PE, nullptr, Vp16, PE, cbv, MK, PE, PE);

    // 3) fused cross attention -> Op16 (+ stats)
    flash2_kernel<<<dim3(PLQ / 64, PH, PB), 128, 40960>>>(
        Qp16, Kp16, Vp16, Op16, sm, sl, PLK, 0, q_len);

    // 4) attention weights output
    weights_flash_kernel<<<dim3(PLQ / 64, PB, 8), 256, 86016>>>(
        Qp16, Kp16, sm, sl, q_len, out_w);

    // 5) cross out-projection
    launch_gemm(Op16, PE, w16 + 3*PE*PE, PE, Pp, nullptr, PE, cbo, MQ, PE, PE);

    // 6) x1 = LN(silu(cross + qm))
    add_silu_ln_kernel<<<MQ, 128>>>(Pp, QM, g_cross, b_cross, X1, X116, q_len, 0);

    // 7) FFN + LN
    launch_gemm(X116, PE, w16 + 8*PE*PE, PE, Fb, nullptr, PHID, bf, MQ, PHID, PE);
    add_silu_ln_kernel<<<MQ, 128>>>(X1, Fb, g_ffn, b_ffn, X2, X216, q_len, 0);

    // 8) self projections (Q prescaled by 1/8)
    launch_gemm(X216, PHID, w16 + 4*PE*PE, PHID, nullptr, Qp16, PHID, sbq, MQ, PHID, PHID, 0.125f);
    launch_gemm(X216, PHID, w16 + 5*PE*PE, PHID, nullptr, Kp16, PHID, sbk, MQ, PHID, PHID);
    launch_gemm(X216, PHID, w16 + 6*PE*PE, PHID, nullptr, Vp16, PHID, sbv, MQ, PHID, PHID);

    // 9) fused self attention (masked keys) -> Op16
    flash2_kernel<<<dim3(PLQ / 64, PH, PB), 128, 40960>>>(
        Qp16, Kp16, Vp16, Op16, nullptr, nullptr, PLQ, 1, q_len);

    // 10) self out-projection
    launch_gemm(Op16, PHID, w16 + 7*PE*PE, PHID, Pp, nullptr, PHID, sbo, MQ, PHID, PHID);

    // 11) final LN, invalid rows zeroed
    add_silu_ln_kernel<<<MQ, 128>>>(X2, Pp, g_self, b_self, out_q, nullptr, q_len, 1);
}